// round 7
// baseline (speedup 1.0000x reference)
#include <cuda_runtime.h>
#include <math.h>
#include <float.h>
#include <stdint.h>

#define B_ 2
#define T_ 2048
#define C_ 2048
#define H_ 16
#define D_ 128
#define F_ (3*C_)

// ---------------- scratch ----------------
__device__ float g_qkv[(size_t)B_ * T_ * F_];      // raw fp32 GEMM output
__device__ float g_q[(size_t)B_ * H_ * T_ * D_];   // tf32-rounded
__device__ float g_k[(size_t)B_ * H_ * T_ * D_];   // tf32-rounded
__device__ float g_v[(size_t)B_ * H_ * T_ * D_];   // tf32-rounded
__device__ float g_y[(size_t)B_ * T_ * C_];        // tf32-rounded
__device__ float g_xa[(size_t)B_ * T_ * C_];       // tf32-rounded x
__device__ float g_wq[(size_t)F_ * C_];            // tf32-rounded Wqkv
__device__ float g_wp[(size_t)C_ * C_];            // tf32-rounded Wproj

// ---------------- helpers ----------------
#define CVT_TF32(d, s) asm("cvt.rna.tf32.f32 %0, %1;" : "=r"(d) : "f"(s))
__device__ __forceinline__ uint32_t tf32_rn(float x) {
    uint32_t r; CVT_TF32(r, x); return r;
}
__device__ __forceinline__ float tf32f(float x) {
    return __uint_as_float(tf32_rn(x));
}

#define MMA_TF32(c, a, b)                                                     \
  asm volatile(                                                               \
      "mma.sync.aligned.m16n8k8.row.col.f32.tf32.tf32.f32 "                   \
      "{%0,%1,%2,%3}, {%4,%5,%6,%7}, {%8,%9}, {%0,%1,%2,%3};"                 \
      : "+f"((c)[0]), "+f"((c)[1]), "+f"((c)[2]), "+f"((c)[3])                \
      : "r"((a)[0]), "r"((a)[1]), "r"((a)[2]), "r"((a)[3]),                   \
        "r"((b)[0]), "r"((b)[1]))

#define LDSM_X4(r, addr)                                                      \
  asm volatile("ldmatrix.sync.aligned.m8n8.x4.shared.b16 {%0,%1,%2,%3}, [%4];"\
      : "=r"((r)[0]), "=r"((r)[1]), "=r"((r)[2]), "=r"((r)[3])                \
      : "r"(addr))

__device__ __forceinline__ uint32_t smem_u32(const void* p) {
    return (uint32_t)__cvta_generic_to_shared(p);
}
__device__ __forceinline__ void cp16(float* sdst, const float* gsrc) {
    uint32_t s = smem_u32(sdst);
    asm volatile("cp.async.cg.shared.global [%0], [%1], 16;" :: "r"(s), "l"(gsrc));
}
#define CP_COMMIT() asm volatile("cp.async.commit_group;" ::)
#define CP_WAIT1()  asm volatile("cp.async.wait_group 1;" ::)

// ---------------- tf32 pre-round convert ----------------
__global__ __launch_bounds__(256) void cvt_tf32_kernel(const float4* __restrict__ src,
                                                       float4* __restrict__ dst, int n4)
{
    int i = blockIdx.x * blockDim.x + threadIdx.x;
    if (i < n4) {
        float4 v = src[i];
        float4 w = {tf32f(v.x), tf32f(v.y), tf32f(v.z), tf32f(v.w)};
        dst[i] = w;
    }
}

// ---------------- tf32 GEMM (pre-rounded): C[m][n]=sum_k A[m][k]B[n][k] ------
// 128x128 tile, 8 warps (2m x 4n), KS=32, 3-stage cp.async, 1 barrier/iter.
#define GSTR 36
#define GS_SZ (128 * GSTR)          // floats per stage per matrix

__global__ __launch_bounds__(256, 2) void gemm_tf32(const float* __restrict__ A,
                                                    const float* __restrict__ Bm,
                                                    float* __restrict__ Cm,
                                                    int M, int N, int K)
{
    extern __shared__ float gsm[];
    float* As = gsm;                 // [3][128][GSTR]
    float* Bs = gsm + 3 * GS_SZ;     // [3][128][GSTR]

    const int tid  = threadIdx.x;
    const int warp = tid >> 5;
    const int lane = tid & 31;
    const int g    = lane >> 2;
    const int tg   = lane & 3;
    const int lm8  = lane & 7;
    const int lq   = lane >> 3;
    const int wm   = (warp & 1) * 64;
    const int wn   = (warp >> 1) * 32;
    const int m0   = blockIdx.y * 128;
    const int n0   = blockIdx.x * 128;

    const int lrow = tid >> 3;       // 0..31
    const int lc4  = (tid & 7) << 2; // 0,4,..28

    const uint32_t sbA = smem_u32(As);
    const uint32_t sbB = smem_u32(Bs);
    const uint32_t aBase = sbA + (uint32_t)((wm + lm8 + ((lq & 1) << 3)) * GSTR) * 4
                               + ((uint32_t)(lq >> 1) << 4);
    const uint32_t bBase = sbB + (uint32_t)((wn + lm8 + ((lq >> 1) << 3)) * GSTR) * 4
                               + ((uint32_t)(lq & 1) << 4);
    const uint32_t stageBytes = GS_SZ * 4;

    float acc[4][4][4];
#pragma unroll
    for (int mi = 0; mi < 4; mi++)
#pragma unroll
        for (int ni = 0; ni < 4; ni++)
#pragma unroll
            for (int c = 0; c < 4; c++) acc[mi][ni][c] = 0.f;

    auto load_stage = [&](int s, int k0) {
#pragma unroll
        for (int i = 0; i < 4; i++) {
            int row = lrow + i * 32;
            cp16(&As[(size_t)s * GS_SZ + row * GSTR + lc4],
                 A + (size_t)(m0 + row) * K + k0 + lc4);
            cp16(&Bs[(size_t)s * GS_SZ + row * GSTR + lc4],
                 Bm + (size_t)(n0 + row) * K + k0 + lc4);
        }
    };

    load_stage(0, 0);  CP_COMMIT();
    load_stage(1, 32); CP_COMMIT();
    CP_WAIT1();                      // stage 0 ready
    __syncthreads();

    const int nK = K / 32;
    int cur = 0, nxt = 2;
    for (int kt = 0; kt < nK; kt++) {
        // prefetch kt+2 into slot (kt+2)%3 (== slot consumed at kt-1; fenced)
        if (kt + 2 < nK) load_stage(nxt, (kt + 2) * 32);
        CP_COMMIT();

        const uint32_t sOff = (uint32_t)cur * stageBytes;
#pragma unroll
        for (int ks = 0; ks < 4; ks++) {
            uint32_t af[4][4];
#pragma unroll
            for (int mi = 0; mi < 4; mi++)
                LDSM_X4(af[mi], aBase + sOff + (uint32_t)(mi * 16 * GSTR * 4) + ks * 32);
#pragma unroll
            for (int p = 0; p < 2; p++) {
                uint32_t bq[4];
                LDSM_X4(bq, bBase + sOff + (uint32_t)(p * 16 * GSTR * 4) + ks * 32);
#pragma unroll
                for (int mi = 0; mi < 4; mi++) {
                    MMA_TF32(acc[mi][2 * p],     af[mi], bq);
                    MMA_TF32(acc[mi][2 * p + 1], af[mi], bq + 2);
                }
            }
        }

        CP_WAIT1();                  // stage kt+1 ready
        __syncthreads();             // single barrier per iteration
        cur = (cur == 2) ? 0 : cur + 1;
        nxt = (nxt == 2) ? 0 : nxt + 1;
    }

#pragma unroll
    for (int mi = 0; mi < 4; mi++) {
#pragma unroll
        for (int ni = 0; ni < 4; ni++) {
            const int r = m0 + wm + mi * 16 + g;
            const int c = n0 + wn + ni * 8 + 2 * tg;
            float2 v0 = {acc[mi][ni][0], acc[mi][ni][1]};
            float2 v1 = {acc[mi][ni][2], acc[mi][ni][3]};
            *(float2*)&Cm[(size_t)r * N + c]       = v0;
            *(float2*)&Cm[(size_t)(r + 8) * N + c] = v1;
        }
    }
}

// ---------------- RoPE + split + gain-fold (emits tf32-rounded q/k/v) --------
__global__ __launch_bounds__(256) void rope_kernel(const float* __restrict__ gain,
                                                   const float* __restrict__ cosb,
                                                   const float* __restrict__ sinb)
{
    int idx = blockIdx.x * blockDim.x + threadIdx.x;
    int d = idx & 63;
    int h = (idx >> 6) & 15;
    int t = (idx >> 10) & 2047;
    int b = idx >> 21;

    size_t base = ((size_t)(b * T_ + t)) * F_ + h * D_;
    float c = cosb[t * 64 + d];
    float s = sinb[t * 64 + d];

    float q1 = g_qkv[base + d],            q2 = g_qkv[base + d + 64];
    float k1 = g_qkv[base + C_ + d],       k2 = g_qkv[base + C_ + d + 64];
    float v1 = g_qkv[base + 2 * C_ + d],   v2 = g_qkv[base + 2 * C_ + d + 64];

    float gn = gain[h] * rsqrtf((float)D_);
    size_t ob = ((size_t)((b * H_ + h) * T_ + t)) * D_;

    g_q[ob + d]      = tf32f((q1 * c - q2 * s) * gn);
    g_q[ob + d + 64] = tf32f((q2 * c + q1 * s) * gn);
    g_k[ob + d]      = tf32f(k1 * c - k2 * s);
    g_k[ob + d + 64] = tf32f(k2 * c + k1 * s);
    g_v[ob + d]      = tf32f(v1);
    g_v[ob + d + 64] = tf32f(v2);
}

// ---------------- tensor-core causal flash attention (tf32) ------------------
// Q tile 128 rows, KEY tile 64, separate K/V buffers, cp.async overlap.
#define QSTR 132
#define KVSTR 136
#define PSTR 68

__global__ __launch_bounds__(256, 1) void attn_tc(float* __restrict__ Y)
{
    extern __shared__ float sm[];
    float* sQ = sm;                          // [128][QSTR]
    float* sK = sQ + 128 * QSTR;             // [64][KVSTR]
    float* sV = sK + 64 * KVSTR;             // [64][KVSTR]
    float* sP = sV + 64 * KVSTR;             // [128][PSTR]

    const int tid  = threadIdx.x;
    const int warp = tid >> 5;
    const int lane = tid & 31;
    const int g    = lane >> 2;
    const int tg   = lane & 3;
    const int lm8  = lane & 7;
    const int lq   = lane >> 3;
    const int qb = blockIdx.x;
    const int h  = blockIdx.y;
    const int b  = blockIdx.z;
    const int q0 = qb * 128;
    const size_t bh = ((size_t)(b * H_ + h)) * T_ * D_;

    const uint32_t qAddr = smem_u32(sQ)
        + (uint32_t)((16 * warp + lm8 + ((lq & 1) << 3)) * QSTR) * 4
        + ((uint32_t)(lq >> 1) << 4);
    const uint32_t kAddr = smem_u32(sK)
        + (uint32_t)((lm8 + ((lq >> 1) << 3)) * KVSTR) * 4
        + ((uint32_t)(lq & 1) << 4);
    const uint32_t pAddr = smem_u32(sP)
        + (uint32_t)((16 * warp + lm8 + ((lq & 1) << 3)) * PSTR) * 4
        + ((uint32_t)(lq >> 1) << 4);

    // load Q tile (already tf32)
    for (int i = 0; i < 16; i++) {
        int e = tid + i * 256;
        int row = e >> 5;
        int col = (e & 31) * 4;
        float4 v = *(const float4*)(g_q + bh + (size_t)(q0 + row) * D_ + col);
        *(float4*)&sQ[row * QSTR + col] = v;
    }

    float yacc[16][4];
#pragma unroll
    for (int nt = 0; nt < 16; nt++)
#pragma unroll
        for (int c = 0; c < 4; c++) yacc[nt][c] = 0.f;
    float m0 = -1e30f, m1 = -1e30f, l0 = 0.f, l1 = 0.f;

    float* pw0 = sP + (size_t)(16 * warp + g) * PSTR;
    float* pw1 = pw0 + 8 * PSTR;

    // loader lambdas: 64 rows x 32 float4 = 2048 chunks / 256 thr = 8 each
    const int lrow = tid >> 5;        // 0..7
    const int lcol = (tid & 31) * 4;  // 0..124
    auto load_k = [&](int k0) {
#pragma unroll
        for (int i = 0; i < 8; i++)
            cp16(&sK[(lrow + i * 8) * KVSTR + lcol],
                 g_k + bh + (size_t)(k0 + lrow + i * 8) * D_ + lcol);
    };
    auto load_v = [&](int k0) {
#pragma unroll
        for (int i = 0; i < 8; i++)
            cp16(&sV[(lrow + i * 8) * KVSTR + lcol],
                 g_v + bh + (size_t)(k0 + lrow + i * 8) * D_ + lcol);
    };

    const int ntiles = 2 * (qb + 1);
    load_k(0); CP_COMMIT();           // prologue: K_0 in flight

    for (int kt = 0; kt < ntiles; kt++) {
        const int k0 = kt * 64;

        load_v(k0); CP_COMMIT();      // V_kt overlaps nothing behind it; bufV free
        CP_WAIT1();                   // K_kt ready (pending: V_kt)
        __syncthreads();

        // S = Q K^T  (128 x 64)
        float sacc[8][4];
#pragma unroll
        for (int nt = 0; nt < 8; nt++)
#pragma unroll
            for (int c = 0; c < 4; c++) sacc[nt][c] = 0.f;

#pragma unroll
        for (int ks = 0; ks < 16; ks++) {
            uint32_t a[4];
            LDSM_X4(a, qAddr + ks * 32);
#pragma unroll
            for (int p = 0; p < 4; p++) {
                uint32_t bq[4];
                LDSM_X4(bq, kAddr + (uint32_t)(p * 16 * KVSTR * 4) + ks * 32);
                MMA_TF32(sacc[2 * p],     a, bq);
                MMA_TF32(sacc[2 * p + 1], a, bq + 2);
            }
        }

        // causal mask (last two tiles of this q-block)
        if (kt >= 2 * qb) {
            const int r0g = q0 + 16 * warp + g;
            const int r1g = r0g + 8;
#pragma unroll
            for (int nt = 0; nt < 8; nt++) {
                int c0 = k0 + nt * 8 + 2 * tg;
                if (c0     > r0g) sacc[nt][0] = -1e30f;
                if (c0 + 1 > r0g) sacc[nt][1] = -1e30f;
                if (c0     > r1g) sacc[nt][2] = -1e30f;
                if (c0 + 1 > r1g) sacc[nt][3] = -1e30f;
            }
        }

        // online softmax over 64 keys
        float mx0 = -1e30f, mx1 = -1e30f;
#pragma unroll
        for (int nt = 0; nt < 8; nt++) {
            mx0 = fmaxf(mx0, fmaxf(sacc[nt][0], sacc[nt][1]));
            mx1 = fmaxf(mx1, fmaxf(sacc[nt][2], sacc[nt][3]));
        }
        mx0 = fmaxf(mx0, __shfl_xor_sync(0xffffffffu, mx0, 1));
        mx0 = fmaxf(mx0, __shfl_xor_sync(0xffffffffu, mx0, 2));
        mx1 = fmaxf(mx1, __shfl_xor_sync(0xffffffffu, mx1, 1));
        mx1 = fmaxf(mx1, __shfl_xor_sync(0xffffffffu, mx1, 2));

        float nm0 = fmaxf(m0, mx0), nm1 = fmaxf(m1, mx1);
        float cf0 = __expf(m0 - nm0), cf1 = __expf(m1 - nm1);
        m0 = nm0; m1 = nm1;

        float rs0 = 0.f, rs1 = 0.f;
#pragma unroll
        for (int nt = 0; nt < 8; nt++) {
            sacc[nt][0] = __expf(sacc[nt][0] - nm0);
            sacc[nt][1] = __expf(sacc[nt][1] - nm0);
            sacc[nt][2] = __expf(sacc[nt][2] - nm1);
            sacc[nt][3] = __expf(sacc[nt][3] - nm1);
            rs0 += sacc[nt][0] + sacc[nt][1];
            rs1 += sacc[nt][2] + sacc[nt][3];
        }
        rs0 += __shfl_xor_sync(0xffffffffu, rs0, 1);
        rs0 += __shfl_xor_sync(0xffffffffu, rs0, 2);
        rs1 += __shfl_xor_sync(0xffffffffu, rs1, 1);
        rs1 += __shfl_xor_sync(0xffffffffu, rs1, 2);
        l0 = l0 * cf0 + rs0;
        l1 = l1 * cf1 + rs1;

#pragma unroll
        for (int nt = 0; nt < 16; nt++) {
            yacc[nt][0] *= cf0; yacc[nt][1] *= cf0;
            yacc[nt][2] *= cf1; yacc[nt][3] *= cf1;
        }

        // stage P (tf32 RN), [q][key] stride PSTR
#pragma unroll
        for (int nt = 0; nt < 8; nt++) {
            int col = nt * 8 + 2 * tg;
            *(float2*)&pw0[col] = make_float2(tf32f(sacc[nt][0]), tf32f(sacc[nt][1]));
            *(float2*)&pw1[col] = make_float2(tf32f(sacc[nt][2]), tf32f(sacc[nt][3]));
        }
        __syncthreads();              // sK free + sP visible

        if (kt + 1 < ntiles) load_k(k0 + 64);   // K_{kt+1} overlaps PV compute
        CP_COMMIT();
        CP_WAIT1();                   // V_kt ready (pending: K_{kt+1})
        __syncthreads();

        // yacc += P V   (128x64 @ 64x128)
#pragma unroll
        for (int ks = 0; ks < 8; ks++) {
            const int kk = ks * 8;
            uint32_t a[4];
            LDSM_X4(a, pAddr + ks * 32);
#pragma unroll
            for (int nt = 0; nt < 16; nt++) {
                uint32_t bfr[2];
                bfr[0] = __float_as_uint(sV[(size_t)(kk + tg) * KVSTR + nt * 8 + g]);
                bfr[1] = __float_as_uint(sV[(size_t)(kk + tg + 4) * KVSTR + nt * 8 + g]);
                MMA_TF32(yacc[nt], a, bfr);
            }
        }
        __syncthreads();              // sV free for next iteration's load_v
    }

    // epilogue: tf32-rounded y (feeds proj GEMM directly)
    const float inv0 = 1.f / l0;
    const float inv1 = 1.f / l1;
    const int r0g = q0 + 16 * warp + g;
    const int r1g = r0g + 8;
#pragma unroll
    for (int nt = 0; nt < 16; nt++) {
        int col = h * D_ + nt * 8 + 2 * tg;
        float2 v0 = {tf32f(yacc[nt][0] * inv0), tf32f(yacc[nt][1] * inv0)};
        float2 v1 = {tf32f(yacc[nt][2] * inv1), tf32f(yacc[nt][3] * inv1)};
        *(float2*)&Y[(size_t)(b * T_ + r0g) * C_ + col] = v0;
        *(float2*)&Y[(size_t)(b * T_ + r1g) * C_ + col] = v1;
    }
}

// ---------------- launch ----------------
extern "C" void kernel_launch(void* const* d_in, const int* in_sizes, int n_in,
                              void* d_out, int out_size)
{
    const float* x     = (const float*)d_in[0];
    const float* Wqkv  = (const float*)d_in[1];
    const float* Wproj = (const float*)d_in[2];
    const float* gain  = (const float*)d_in[3];
    const float* cosb  = (const float*)d_in[4];
    const float* sinb  = (const float*)d_in[5];
    float* out = (float*)d_out;

    float *qkv, *y, *xa, *wq, *wp;
    cudaGetSymbolAddress((void**)&qkv, g_qkv);
    cudaGetSymbolAddress((void**)&y,   g_y);
    cudaGetSymbolAddress((void**)&xa,  g_xa);
    cudaGetSymbolAddress((void**)&wq,  g_wq);
    cudaGetSymbolAddress((void**)&wp,  g_wp);

    const size_t gemm_smem = (size_t)6 * GS_SZ * sizeof(float);   // 110592
    cudaFuncSetAttribute(gemm_tf32, cudaFuncAttributeMaxDynamicSharedMemorySize, (int)gemm_smem);

    // 0) pre-round inputs to tf32
    {
        int n4x = (B_ * T_ * C_) / 4;
        cvt_tf32_kernel<<<(n4x + 255) / 256, 256>>>((const float4*)x, (float4*)xa, n4x);
        int n4q = (F_ * C_) / 4;
        cvt_tf32_kernel<<<(n4q + 255) / 256, 256>>>((const float4*)Wqkv, (float4*)wq, n4q);
        int n4p = (C_ * C_) / 4;
        cvt_tf32_kernel<<<(n4p + 255) / 256, 256>>>((const float4*)Wproj, (float4*)wp, n4p);
    }

    // 1) QKV GEMM: [4096,2048] x [6144,2048]^T -> [4096,6144]
    {
        dim3 grid(F_ / 128, (B_ * T_) / 128);
        gemm_tf32<<<grid, 256, gemm_smem>>>(xa, wq, qkv, B_ * T_, F_, C_);
    }

    // 2) RoPE + split + gain (emits tf32)
    {
        int total = B_ * T_ * H_ * 64;
        rope_kernel<<<total / 256, 256>>>(gain, cosb, sinb);
    }

    // 3) attention (tensor core, K/V double-buffered overlap)
    {
        size_t smem = (size_t)(128 * QSTR + 2 * 64 * KVSTR + 128 * PSTR) * sizeof(float); // 172032
        cudaFuncSetAttribute(attn_tc, cudaFuncAttributeMaxDynamicSharedMemorySize, (int)smem);
        dim3 grid(T_ / 128, H_, B_);
        attn_tc<<<grid, 256, smem>>>(y);
    }

    // 4) output projection: [4096,2048] x [2048,2048]^T -> out
    {
        dim3 grid(C_ / 128, (B_ * T_) / 128);
        gemm_tf32<<<grid, 256, gemm_smem>>>(y, wp, out, B_ * T_, C_, C_);
    }
}

// round 8
// speedup vs baseline: 1.0119x; 1.0119x over previous
#include <cuda_runtime.h>
#include <math.h>
#include <float.h>
#include <stdint.h>

#define B_ 2
#define T_ 2048
#define C_ 2048
#define H_ 16
#define D_ 128
#define F_ (3*C_)

// ---------------- scratch ----------------
__device__ float g_qkv[(size_t)B_ * T_ * F_];      // raw fp32 GEMM output
__device__ float g_q[(size_t)B_ * H_ * T_ * D_];   // tf32-rounded
__device__ float g_k[(size_t)B_ * H_ * T_ * D_];   // tf32-rounded
__device__ float g_v[(size_t)B_ * H_ * T_ * D_];   // tf32-rounded
__device__ float g_y[(size_t)B_ * T_ * C_];        // tf32-rounded
__device__ float g_xa[(size_t)B_ * T_ * C_];       // tf32-rounded x
__device__ float g_wq[(size_t)F_ * C_];            // tf32-rounded Wqkv
__device__ float g_wp[(size_t)C_ * C_];            // tf32-rounded Wproj

// ---------------- helpers ----------------
#define CVT_TF32(d, s) asm("cvt.rna.tf32.f32 %0, %1;" : "=r"(d) : "f"(s))
__device__ __forceinline__ uint32_t tf32_rn(float x) {
    uint32_t r; CVT_TF32(r, x); return r;
}
__device__ __forceinline__ float tf32f(float x) {
    return __uint_as_float(tf32_rn(x));
}

#define MMA_TF32(c, a, b)                                                     \
  asm volatile(                                                               \
      "mma.sync.aligned.m16n8k8.row.col.f32.tf32.tf32.f32 "                   \
      "{%0,%1,%2,%3}, {%4,%5,%6,%7}, {%8,%9}, {%0,%1,%2,%3};"                 \
      : "+f"((c)[0]), "+f"((c)[1]), "+f"((c)[2]), "+f"((c)[3])                \
      : "r"((a)[0]), "r"((a)[1]), "r"((a)[2]), "r"((a)[3]),                   \
        "r"((b)[0]), "r"((b)[1]))

#define LDSM_X4(r, addr)                                                      \
  asm volatile("ldmatrix.sync.aligned.m8n8.x4.shared.b16 {%0,%1,%2,%3}, [%4];"\
      : "=r"((r)[0]), "=r"((r)[1]), "=r"((r)[2]), "=r"((r)[3])                \
      : "r"(addr))

__device__ __forceinline__ uint32_t smem_u32(const void* p) {
    return (uint32_t)__cvta_generic_to_shared(p);
}
__device__ __forceinline__ void cp16(float* sdst, const float* gsrc) {
    uint32_t s = smem_u32(sdst);
    asm volatile("cp.async.cg.shared.global [%0], [%1], 16;" :: "r"(s), "l"(gsrc));
}
#define CP_COMMIT() asm volatile("cp.async.commit_group;" ::)
#define CP_WAIT1()  asm volatile("cp.async.wait_group 1;" ::)

// ---------------- tf32 pre-round convert ----------------
__global__ __launch_bounds__(256) void cvt_tf32_kernel(const float4* __restrict__ src,
                                                       float4* __restrict__ dst, int n4)
{
    int i = blockIdx.x * blockDim.x + threadIdx.x;
    if (i < n4) {
        float4 v = src[i];
        float4 w = {tf32f(v.x), tf32f(v.y), tf32f(v.z), tf32f(v.w)};
        dst[i] = w;
    }
}

// ---------------- tf32 GEMM (pre-rounded): C[m][n]=sum_k A[m][k]B[n][k] ------
// CTA tile 128x128, 4 warps (2m x 2n), warp tile 64x64, KS=32, 2-stage cp.async.
// 128 threads/CTA, 2 CTAs/SM: regs up to ~255 OK, smem 2x73728=147KB/SM.
#define GSTR 36
#define GS_SZ (128 * GSTR)          // floats per stage per matrix

__global__ __launch_bounds__(128, 2) void gemm_tf32(const float* __restrict__ A,
                                                    const float* __restrict__ Bm,
                                                    float* __restrict__ Cm,
                                                    int M, int N, int K)
{
    extern __shared__ float gsm[];
    float* As = gsm;                 // [2][128][GSTR]
    float* Bs = gsm + 2 * GS_SZ;     // [2][128][GSTR]

    const int tid  = threadIdx.x;
    const int warp = tid >> 5;
    const int lane = tid & 31;
    const int g    = lane >> 2;
    const int tg   = lane & 3;
    const int lm8  = lane & 7;
    const int lq   = lane >> 3;      // 0..3
    const int wm   = (warp >> 1) * 64;
    const int wn   = (warp & 1) * 64;
    const int m0   = blockIdx.y * 128;
    const int n0   = blockIdx.x * 128;

    const int lrow = tid >> 3;       // 0..15
    const int lc4  = (tid & 7) << 2; // 0,4,..28

    const uint32_t sbA = smem_u32(As);
    const uint32_t sbB = smem_u32(Bs);
    const uint32_t aBase = sbA + (uint32_t)((wm + lm8 + ((lq & 1) << 3)) * GSTR) * 4
                               + ((uint32_t)(lq >> 1) << 4);
    const uint32_t bBase = sbB + (uint32_t)((wn + lm8 + ((lq >> 1) << 3)) * GSTR) * 4
                               + ((uint32_t)(lq & 1) << 4);
    const uint32_t stageBytes = GS_SZ * 4;

    float acc[4][8][4];
#pragma unroll
    for (int mi = 0; mi < 4; mi++)
#pragma unroll
        for (int ni = 0; ni < 8; ni++)
#pragma unroll
            for (int c = 0; c < 4; c++) acc[mi][ni][c] = 0.f;

    // loader: A 128 rows x 8 float4 = 1024 chunks / 128 thr = 8 each; same B
    auto load_stage = [&](int s, int k0) {
#pragma unroll
        for (int i = 0; i < 8; i++) {
            int row = lrow + i * 16;
            cp16(&As[(size_t)s * GS_SZ + row * GSTR + lc4],
                 A + (size_t)(m0 + row) * K + k0 + lc4);
            cp16(&Bs[(size_t)s * GS_SZ + row * GSTR + lc4],
                 Bm + (size_t)(n0 + row) * K + k0 + lc4);
        }
    };

    load_stage(0, 0);  CP_COMMIT();
    load_stage(1, 32); CP_COMMIT();
    CP_WAIT1();
    __syncthreads();

    const int nK = K / 32;
    int cur = 0;
    for (int kt = 0; kt < nK; kt++) {
        const uint32_t sOff = (uint32_t)cur * stageBytes;
#pragma unroll
        for (int ks = 0; ks < 4; ks++) {
            uint32_t af[4][4], bq[4][4];
#pragma unroll
            for (int mi = 0; mi < 4; mi++)
                LDSM_X4(af[mi], aBase + sOff + (uint32_t)(mi * 16 * GSTR * 4) + ks * 32);
#pragma unroll
            for (int p = 0; p < 4; p++)
                LDSM_X4(bq[p], bBase + sOff + (uint32_t)(p * 16 * GSTR * 4) + ks * 32);
#pragma unroll
            for (int mi = 0; mi < 4; mi++)
#pragma unroll
                for (int p = 0; p < 4; p++) {
                    MMA_TF32(acc[mi][2 * p],     af[mi], bq[p]);
                    MMA_TF32(acc[mi][2 * p + 1], af[mi], bq[p] + 2);
                }
        }
        __syncthreads();
        if (kt + 2 < nK) load_stage(cur, (kt + 2) * 32);
        CP_COMMIT();
        CP_WAIT1();
        __syncthreads();
        cur ^= 1;
    }

#pragma unroll
    for (int mi = 0; mi < 4; mi++) {
#pragma unroll
        for (int ni = 0; ni < 8; ni++) {
            const int r = m0 + wm + mi * 16 + g;
            const int c = n0 + wn + ni * 8 + 2 * tg;
            float2 v0 = {acc[mi][ni][0], acc[mi][ni][1]};
            float2 v1 = {acc[mi][ni][2], acc[mi][ni][3]};
            *(float2*)&Cm[(size_t)r * N + c]       = v0;
            *(float2*)&Cm[(size_t)(r + 8) * N + c] = v1;
        }
    }
}

// ---------------- RoPE + split + gain-fold (emits tf32-rounded q/k/v) --------
__global__ __launch_bounds__(256) void rope_kernel(const float* __restrict__ gain,
                                                   const float* __restrict__ cosb,
                                                   const float* __restrict__ sinb)
{
    int idx = blockIdx.x * blockDim.x + threadIdx.x;
    int d = idx & 63;
    int h = (idx >> 6) & 15;
    int t = (idx >> 10) & 2047;
    int b = idx >> 21;

    size_t base = ((size_t)(b * T_ + t)) * F_ + h * D_;
    float c = cosb[t * 64 + d];
    float s = sinb[t * 64 + d];

    float q1 = g_qkv[base + d],            q2 = g_qkv[base + d + 64];
    float k1 = g_qkv[base + C_ + d],       k2 = g_qkv[base + C_ + d + 64];
    float v1 = g_qkv[base + 2 * C_ + d],   v2 = g_qkv[base + 2 * C_ + d + 64];

    float gn = gain[h] * rsqrtf((float)D_);
    size_t ob = ((size_t)((b * H_ + h) * T_ + t)) * D_;

    g_q[ob + d]      = tf32f((q1 * c - q2 * s) * gn);
    g_q[ob + d + 64] = tf32f((q2 * c + q1 * s) * gn);
    g_k[ob + d]      = tf32f(k1 * c - k2 * s);
    g_k[ob + d + 64] = tf32f(k2 * c + k1 * s);
    g_v[ob + d]      = tf32f(v1);
    g_v[ob + d + 64] = tf32f(v2);
}

// ---------------- tensor-core causal flash attention (round-6 version) -------
#define QSTR 132
#define KSTR 132
#define VSTR 136
#define PSTR 132

__global__ __launch_bounds__(256, 1) void attn_tc(float* __restrict__ Y)
{
    extern __shared__ float sm[];
    float* sQ  = sm;                         // [128][QSTR] tf32
    float* sKV = sm + 128 * QSTR;            // K stride KSTR / V stride VSTR
    float* sP  = sKV + 128 * VSTR;           // [128][PSTR] tf32

    const int tid  = threadIdx.x;
    const int warp = tid >> 5;
    const int lane = tid & 31;
    const int g    = lane >> 2;
    const int tg   = lane & 3;
    const int lm8  = lane & 7;
    const int lq   = lane >> 3;
    const int qb = blockIdx.x;
    const int h  = blockIdx.y;
    const int b  = blockIdx.z;
    const int q0 = qb * 128;
    const size_t bh = ((size_t)(b * H_ + h)) * T_ * D_;

    const uint32_t qAddr = smem_u32(sQ)
        + (uint32_t)((16 * warp + lm8 + ((lq & 1) << 3)) * QSTR) * 4
        + ((uint32_t)(lq >> 1) << 4);
    const uint32_t kAddr = smem_u32(sKV)
        + (uint32_t)((lm8 + ((lq >> 1) << 3)) * KSTR) * 4
        + ((uint32_t)(lq & 1) << 4);
    const uint32_t pAddr = smem_u32(sP)
        + (uint32_t)((16 * warp + lm8 + ((lq & 1) << 3)) * PSTR) * 4
        + ((uint32_t)(lq >> 1) << 4);

    // load Q tile (already tf32)
    for (int i = 0; i < 16; i++) {
        int e = tid + i * 256;
        int row = e >> 5;
        int col = (e & 31) * 4;
        float4 v = *(const float4*)(g_q + bh + (size_t)(q0 + row) * D_ + col);
        *(float4*)&sQ[row * QSTR + col] = v;
    }

    float yacc[16][4];
#pragma unroll
    for (int nt = 0; nt < 16; nt++)
#pragma unroll
        for (int c = 0; c < 4; c++) yacc[nt][c] = 0.f;
    float m0 = -1e30f, m1 = -1e30f, l0 = 0.f, l1 = 0.f;

    float* pw0 = sP + (size_t)(16 * warp + g) * PSTR;
    float* pw1 = pw0 + 8 * PSTR;

    for (int kt = 0; kt <= qb; kt++) {
        const int k0 = kt * 128;

        // load K (already tf32), [key][d]
        for (int i = 0; i < 16; i++) {
            int e = tid + i * 256;
            int row = e >> 5;
            int col = (e & 31) * 4;
            float4 v = *(const float4*)(g_k + bh + (size_t)(k0 + row) * D_ + col);
            *(float4*)&sKV[row * KSTR + col] = v;
        }
        __syncthreads();

        // S = Q K^T
        float sacc[16][4];
#pragma unroll
        for (int nt = 0; nt < 16; nt++)
#pragma unroll
            for (int c = 0; c < 4; c++) sacc[nt][c] = 0.f;

#pragma unroll
        for (int ks = 0; ks < 16; ks++) {
            uint32_t a[4];
            LDSM_X4(a, qAddr + ks * 32);
#pragma unroll
            for (int p = 0; p < 8; p++) {
                uint32_t bq[4];
                LDSM_X4(bq, kAddr + (uint32_t)(p * 16 * KSTR * 4) + ks * 32);
                MMA_TF32(sacc[2 * p],     a, bq);
                MMA_TF32(sacc[2 * p + 1], a, bq + 2);
            }
        }

        // causal mask on diagonal tile
        if (kt == qb) {
            const int r0g = q0 + 16 * warp + g;
            const int r1g = r0g + 8;
#pragma unroll
            for (int nt = 0; nt < 16; nt++) {
                int c0 = k0 + nt * 8 + 2 * tg;
                if (c0     > r0g) sacc[nt][0] = -1e30f;
                if (c0 + 1 > r0g) sacc[nt][1] = -1e30f;
                if (c0     > r1g) sacc[nt][2] = -1e30f;
                if (c0 + 1 > r1g) sacc[nt][3] = -1e30f;
            }
        }

        // online softmax
        float mx0 = -1e30f, mx1 = -1e30f;
#pragma unroll
        for (int nt = 0; nt < 16; nt++) {
            mx0 = fmaxf(mx0, fmaxf(sacc[nt][0], sacc[nt][1]));
            mx1 = fmaxf(mx1, fmaxf(sacc[nt][2], sacc[nt][3]));
        }
        mx0 = fmaxf(mx0, __shfl_xor_sync(0xffffffffu, mx0, 1));
        mx0 = fmaxf(mx0, __shfl_xor_sync(0xffffffffu, mx0, 2));
        mx1 = fmaxf(mx1, __shfl_xor_sync(0xffffffffu, mx1, 1));
        mx1 = fmaxf(mx1, __shfl_xor_sync(0xffffffffu, mx1, 2));

        float nm0 = fmaxf(m0, mx0), nm1 = fmaxf(m1, mx1);
        float cf0 = __expf(m0 - nm0), cf1 = __expf(m1 - nm1);
        m0 = nm0; m1 = nm1;

        float rs0 = 0.f, rs1 = 0.f;
#pragma unroll
        for (int nt = 0; nt < 16; nt++) {
            sacc[nt][0] = __expf(sacc[nt][0] - nm0);
            sacc[nt][1] = __expf(sacc[nt][1] - nm0);
            sacc[nt][2] = __expf(sacc[nt][2] - nm1);
            sacc[nt][3] = __expf(sacc[nt][3] - nm1);
            rs0 += sacc[nt][0] + sacc[nt][1];
            rs1 += sacc[nt][2] + sacc[nt][3];
        }
        rs0 += __shfl_xor_sync(0xffffffffu, rs0, 1);
        rs0 += __shfl_xor_sync(0xffffffffu, rs0, 2);
        rs1 += __shfl_xor_sync(0xffffffffu, rs1, 1);
        rs1 += __shfl_xor_sync(0xffffffffu, rs1, 2);
        l0 = l0 * cf0 + rs0;
        l1 = l1 * cf1 + rs1;

#pragma unroll
        for (int nt = 0; nt < 16; nt++) {
            yacc[nt][0] *= cf0; yacc[nt][1] *= cf0;
            yacc[nt][2] *= cf1; yacc[nt][3] *= cf1;
        }

        // stage P (tf32 RN)
#pragma unroll
        for (int nt = 0; nt < 16; nt++) {
            int col = nt * 8 + 2 * tg;
            *(float2*)&pw0[col] = make_float2(tf32f(sacc[nt][0]), tf32f(sacc[nt][1]));
            *(float2*)&pw1[col] = make_float2(tf32f(sacc[nt][2]), tf32f(sacc[nt][3]));
        }
        __syncwarp();
        __syncthreads();

        // load V (already tf32), [key][d]
        for (int i = 0; i < 16; i++) {
            int e = tid + i * 256;
            int row = e >> 5;
            int col = (e & 31) * 4;
            float4 v = *(const float4*)(g_v + bh + (size_t)(k0 + row) * D_ + col);
            *(float4*)&sKV[row * VSTR + col] = v;
        }
        __syncthreads();

        // yacc += P V
#pragma unroll
        for (int ks = 0; ks < 16; ks++) {
            const int kk = ks * 8;
            uint32_t a[4];
            LDSM_X4(a, pAddr + ks * 32);
#pragma unroll
            for (int nt = 0; nt < 16; nt++) {
                uint32_t bfr[2];
                bfr[0] = __float_as_uint(sKV[(size_t)(kk + tg) * VSTR + nt * 8 + g]);
                bfr[1] = __float_as_uint(sKV[(size_t)(kk + tg + 4) * VSTR + nt * 8 + g]);
                MMA_TF32(yacc[nt], a, bfr);
            }
        }
        __syncthreads();
    }

    // epilogue: tf32-rounded y (feeds proj GEMM directly)
    const float inv0 = 1.f / l0;
    const float inv1 = 1.f / l1;
    const int r0g = q0 + 16 * warp + g;
    const int r1g = r0g + 8;
#pragma unroll
    for (int nt = 0; nt < 16; nt++) {
        int col = h * D_ + nt * 8 + 2 * tg;
        float2 v0 = {tf32f(yacc[nt][0] * inv0), tf32f(yacc[nt][1] * inv0)};
        float2 v1 = {tf32f(yacc[nt][2] * inv1), tf32f(yacc[nt][3] * inv1)};
        *(float2*)&Y[(size_t)(b * T_ + r0g) * C_ + col] = v0;
        *(float2*)&Y[(size_t)(b * T_ + r1g) * C_ + col] = v1;
    }
}

// ---------------- launch ----------------
extern "C" void kernel_launch(void* const* d_in, const int* in_sizes, int n_in,
                              void* d_out, int out_size)
{
    const float* x     = (const float*)d_in[0];
    const float* Wqkv  = (const float*)d_in[1];
    const float* Wproj = (const float*)d_in[2];
    const float* gain  = (const float*)d_in[3];
    const float* cosb  = (const float*)d_in[4];
    const float* sinb  = (const float*)d_in[5];
    float* out = (float*)d_out;

    float *qkv, *y, *xa, *wq, *wp;
    cudaGetSymbolAddress((void**)&qkv, g_qkv);
    cudaGetSymbolAddress((void**)&y,   g_y);
    cudaGetSymbolAddress((void**)&xa,  g_xa);
    cudaGetSymbolAddress((void**)&wq,  g_wq);
    cudaGetSymbolAddress((void**)&wp,  g_wp);

    const size_t gemm_smem = (size_t)4 * GS_SZ * sizeof(float);   // 73728
    cudaFuncSetAttribute(gemm_tf32, cudaFuncAttributeMaxDynamicSharedMemorySize, (int)gemm_smem);

    // 0) pre-round inputs to tf32
    {
        int n4x = (B_ * T_ * C_) / 4;
        cvt_tf32_kernel<<<(n4x + 255) / 256, 256>>>((const float4*)x, (float4*)xa, n4x);
        int n4q = (F_ * C_) / 4;
        cvt_tf32_kernel<<<(n4q + 255) / 256, 256>>>((const float4*)Wqkv, (float4*)wq, n4q);
        int n4p = (C_ * C_) / 4;
        cvt_tf32_kernel<<<(n4p + 255) / 256, 256>>>((const float4*)Wproj, (float4*)wp, n4p);
    }

    // 1) QKV GEMM: [4096,2048] x [6144,2048]^T -> [4096,6144]
    {
        dim3 grid(F_ / 128, (B_ * T_) / 128);
        gemm_tf32<<<grid, 128, gemm_smem>>>(xa, wq, qkv, B_ * T_, F_, C_);
    }

    // 2) RoPE + split + gain (emits tf32)
    {
        int total = B_ * T_ * H_ * 64;
        rope_kernel<<<total / 256, 256>>>(gain, cosb, sinb);
    }

    // 3) attention (tensor core)
    {
        size_t smem = (size_t)(128 * QSTR + 128 * VSTR + 128 * PSTR) * sizeof(float);
        cudaFuncSetAttribute(attn_tc, cudaFuncAttributeMaxDynamicSharedMemorySize, (int)smem);
        dim3 grid(T_ / 128, H_, B_);
        attn_tc<<<grid, 256, smem>>>(y);
    }

    // 4) output projection: [4096,2048] x [2048,2048]^T -> out
    {
        dim3 grid(C_ / 128, (B_ * T_) / 128);
        gemm_tf32<<<grid, 128, gemm_smem>>>(y, wp, out, B_ * T_, C_, C_);
    }
}

// round 9
// speedup vs baseline: 1.6644x; 1.6448x over previous
#include <cuda_runtime.h>
#include <cuda_fp16.h>
#include <math.h>
#include <float.h>
#include <stdint.h>

#define B_ 2
#define T_ 2048
#define C_ 2048
#define H_ 16
#define D_ 128
#define F_ (3*C_)

// ---------------- scratch ----------------
__device__ float  g_qkv[(size_t)B_ * T_ * F_];      // raw fp32 GEMM output
__device__ __half g_q[(size_t)B_ * H_ * T_ * D_];   // fp16
__device__ __half g_k[(size_t)B_ * H_ * T_ * D_];
__device__ __half g_v[(size_t)B_ * H_ * T_ * D_];
__device__ __half g_y[(size_t)B_ * T_ * C_];
__device__ __half g_xh[(size_t)B_ * T_ * C_];       // fp16 x
__device__ __half g_wq[(size_t)F_ * C_];            // fp16 Wqkv
__device__ __half g_wp[(size_t)C_ * C_];            // fp16 Wproj

// ---------------- helpers ----------------
#define MMA_F16(c, a, b)                                                      \
  asm volatile(                                                               \
      "mma.sync.aligned.m16n8k16.row.col.f32.f16.f16.f32 "                    \
      "{%0,%1,%2,%3}, {%4,%5,%6,%7}, {%8,%9}, {%0,%1,%2,%3};"                 \
      : "+f"((c)[0]), "+f"((c)[1]), "+f"((c)[2]), "+f"((c)[3])                \
      : "r"((a)[0]), "r"((a)[1]), "r"((a)[2]), "r"((a)[3]),                   \
        "r"((b)[0]), "r"((b)[1]))

#define LDSM_X4(r, addr)                                                      \
  asm volatile("ldmatrix.sync.aligned.m8n8.x4.shared.b16 {%0,%1,%2,%3}, [%4];"\
      : "=r"((r)[0]), "=r"((r)[1]), "=r"((r)[2]), "=r"((r)[3])                \
      : "r"(addr))

#define LDSM_X4_T(r, addr)                                                    \
  asm volatile("ldmatrix.sync.aligned.m8n8.x4.trans.shared.b16 {%0,%1,%2,%3}, [%4];"\
      : "=r"((r)[0]), "=r"((r)[1]), "=r"((r)[2]), "=r"((r)[3])                \
      : "r"(addr))

__device__ __forceinline__ uint32_t smem_u32(const void* p) {
    return (uint32_t)__cvta_generic_to_shared(p);
}
__device__ __forceinline__ void cp16(void* sdst, const void* gsrc) {
    uint32_t s = smem_u32(sdst);
    asm volatile("cp.async.cg.shared.global [%0], [%1], 16;" :: "r"(s), "l"(gsrc));
}
#define CP_COMMIT() asm volatile("cp.async.commit_group;" ::)
#define CP_WAIT1()  asm volatile("cp.async.wait_group 1;" ::)

// ---------------- fp32 -> fp16 convert (8 elems/thread) ----------------
__global__ __launch_bounds__(256) void cvt_f16_kernel(const float4* __restrict__ src,
                                                      uint4* __restrict__ dst, int n8)
{
    int i = blockIdx.x * blockDim.x + threadIdx.x;
    if (i < n8) {
        float4 a = src[2 * i];
        float4 b = src[2 * i + 1];
        __half2 h0 = __floats2half2_rn(a.x, a.y);
        __half2 h1 = __floats2half2_rn(a.z, a.w);
        __half2 h2 = __floats2half2_rn(b.x, b.y);
        __half2 h3 = __floats2half2_rn(b.z, b.w);
        uint4 o = {*(uint32_t*)&h0, *(uint32_t*)&h1, *(uint32_t*)&h2, *(uint32_t*)&h3};
        dst[i] = o;
    }
}

// ---------------- fp16 GEMM: C[m][n] = sum_k A[m][k]*B[n][k] -----------------
// CTA 128x128, 8 warps (2m x 4n), warp 64x32, KS=32, 2-stage cp.async.
#define HSTR 40                     // halves per smem row (80B, conflict-free)
#define HS_SZ (128 * HSTR)          // halves per stage per matrix

__global__ __launch_bounds__(256, 2) void gemm_f16(const __half* __restrict__ A,
                                                   const __half* __restrict__ Bm,
                                                   float* __restrict__ Cm,
                                                   int M, int N, int K)
{
    extern __shared__ __half hsm[];
    __half* As = hsm;                // [2][128][HSTR]
    __half* Bs = hsm + 2 * HS_SZ;    // [2][128][HSTR]

    const int tid  = threadIdx.x;
    const int warp = tid >> 5;
    const int lane = tid & 31;
    const int g    = lane >> 2;
    const int tg   = lane & 3;
    const int lm8  = lane & 7;
    const int lq   = lane >> 3;      // 0..3
    const int wm   = (warp & 1) * 64;
    const int wn   = (warp >> 1) * 32;
    const int m0   = blockIdx.y * 128;
    const int n0   = blockIdx.x * 128;

    const uint32_t sbA = smem_u32(As);
    const uint32_t sbB = smem_u32(Bs);
    const uint32_t aBase = sbA + (uint32_t)((wm + lm8 + ((lq & 1) << 3)) * HSTR) * 2
                               + ((uint32_t)(lq >> 1) << 4);
    const uint32_t bBase = sbB + (uint32_t)((wn + lm8 + ((lq >> 1) << 3)) * HSTR) * 2
                               + ((uint32_t)(lq & 1) << 4);
    const uint32_t stageBytes = HS_SZ * 2;

    float acc[4][4][4];
#pragma unroll
    for (int mi = 0; mi < 4; mi++)
#pragma unroll
        for (int ni = 0; ni < 4; ni++)
#pragma unroll
            for (int c = 0; c < 4; c++) acc[mi][ni][c] = 0.f;

    // loader: 128 rows x 4 16B-chunks per matrix = 512 chunks -> 2/thread
    auto load_stage = [&](int s, int k0) {
#pragma unroll
        for (int t = 0; t < 2; t++) {
            int cid = tid + t * 256;
            int row = cid >> 2;
            int ch8 = (cid & 3) * 8;
            cp16(&As[(size_t)s * HS_SZ + row * HSTR + ch8],
                 A + (size_t)(m0 + row) * K + k0 + ch8);
            cp16(&Bs[(size_t)s * HS_SZ + row * HSTR + ch8],
                 Bm + (size_t)(n0 + row) * K + k0 + ch8);
        }
    };

    load_stage(0, 0);  CP_COMMIT();
    load_stage(1, 32); CP_COMMIT();
    CP_WAIT1();
    __syncthreads();

    const int nK = K / 32;
    int cur = 0;
    for (int kt = 0; kt < nK; kt++) {
        const uint32_t sOff = (uint32_t)cur * stageBytes;
#pragma unroll
        for (int ks = 0; ks < 2; ks++) {      // two k16 steps
            uint32_t af[4][4], bq[2][4];
#pragma unroll
            for (int mi = 0; mi < 4; mi++)
                LDSM_X4(af[mi], aBase + sOff + (uint32_t)(mi * 16 * HSTR * 2) + ks * 32);
#pragma unroll
            for (int p = 0; p < 2; p++)
                LDSM_X4(bq[p], bBase + sOff + (uint32_t)(p * 16 * HSTR * 2) + ks * 32);
#pragma unroll
            for (int mi = 0; mi < 4; mi++)
#pragma unroll
                for (int p = 0; p < 2; p++) {
                    MMA_F16(acc[mi][2 * p],     af[mi], bq[p]);
                    MMA_F16(acc[mi][2 * p + 1], af[mi], bq[p] + 2);
                }
        }
        __syncthreads();
        if (kt + 2 < nK) load_stage(cur, (kt + 2) * 32);
        CP_COMMIT();
        CP_WAIT1();
        __syncthreads();
        cur ^= 1;
    }

#pragma unroll
    for (int mi = 0; mi < 4; mi++) {
#pragma unroll
        for (int ni = 0; ni < 4; ni++) {
            const int r = m0 + wm + mi * 16 + g;
            const int c = n0 + wn + ni * 8 + 2 * tg;
            float2 v0 = {acc[mi][ni][0], acc[mi][ni][1]};
            float2 v1 = {acc[mi][ni][2], acc[mi][ni][3]};
            *(float2*)&Cm[(size_t)r * N + c]       = v0;
            *(float2*)&Cm[(size_t)(r + 8) * N + c] = v1;
        }
    }
}

// ---------------- RoPE + split + gain-fold (emits fp16 q/k/v) ----------------
__global__ __launch_bounds__(256) void rope_kernel(const float* __restrict__ gain,
                                                   const float* __restrict__ cosb,
                                                   const float* __restrict__ sinb)
{
    int idx = blockIdx.x * blockDim.x + threadIdx.x;
    int d = idx & 63;
    int h = (idx >> 6) & 15;
    int t = (idx >> 10) & 2047;
    int b = idx >> 21;

    size_t base = ((size_t)(b * T_ + t)) * F_ + h * D_;
    float c = cosb[t * 64 + d];
    float s = sinb[t * 64 + d];

    float q1 = g_qkv[base + d],            q2 = g_qkv[base + d + 64];
    float k1 = g_qkv[base + C_ + d],       k2 = g_qkv[base + C_ + d + 64];
    float v1 = g_qkv[base + 2 * C_ + d],   v2 = g_qkv[base + 2 * C_ + d + 64];

    float gn = gain[h] * rsqrtf((float)D_);
    size_t ob = ((size_t)((b * H_ + h) * T_ + t)) * D_;

    g_q[ob + d]      = __float2half_rn((q1 * c - q2 * s) * gn);
    g_q[ob + d + 64] = __float2half_rn((q2 * c + q1 * s) * gn);
    g_k[ob + d]      = __float2half_rn(k1 * c - k2 * s);
    g_k[ob + d + 64] = __float2half_rn(k2 * c + k1 * s);
    g_v[ob + d]      = __float2half_rn(v1);
    g_v[ob + d + 64] = __float2half_rn(v2);
}

// ---------------- fp16 tensor-core causal flash attention --------------------
#define QH 136    // halves per row (272B stride, conflict-free)

__global__ __launch_bounds__(256, 1) void attn_tc(__half* __restrict__ Y)
{
    extern __shared__ __half ham[];
    __half* sQ  = ham;                       // [128][QH]
    __half* sKV = ham + 128 * QH;            // [128][QH] (K then V)
    __half* sP  = sKV + 128 * QH;            // [128][QH]

    const int tid  = threadIdx.x;
    const int warp = tid >> 5;
    const int lane = tid & 31;
    const int g    = lane >> 2;
    const int tg   = lane & 3;
    const int lm8  = lane & 7;
    const int lq   = lane >> 3;
    const int qb = blockIdx.x;
    const int h  = blockIdx.y;
    const int b  = blockIdx.z;
    const int q0 = qb * 128;
    const size_t bh = ((size_t)(b * H_ + h)) * T_ * D_;

    const uint32_t qAddr = smem_u32(sQ)
        + (uint32_t)((16 * warp + lm8 + ((lq & 1) << 3)) * QH) * 2
        + ((uint32_t)(lq >> 1) << 4);
    const uint32_t kAddr = smem_u32(sKV)
        + (uint32_t)((lm8 + ((lq >> 1) << 3)) * QH) * 2
        + ((uint32_t)(lq & 1) << 4);
    const uint32_t vAddr = smem_u32(sKV)
        + (uint32_t)((lm8 + ((lq & 1) << 3)) * QH) * 2
        + ((uint32_t)(lq >> 1) << 4);
    const uint32_t pAddr = smem_u32(sP)
        + (uint32_t)((16 * warp + lm8 + ((lq & 1) << 3)) * QH) * 2
        + ((uint32_t)(lq >> 1) << 4);

    // load Q tile: 128 rows x 16 uint4 = 2048 -> 8/thread
    for (int i = 0; i < 8; i++) {
        int e = tid + i * 256;
        int row = e >> 4;
        int col = (e & 15) * 8;
        *(uint4*)&sQ[row * QH + col] = *(const uint4*)(g_q + bh + (size_t)(q0 + row) * D_ + col);
    }

    float yacc[16][4];
#pragma unroll
    for (int nt = 0; nt < 16; nt++)
#pragma unroll
        for (int c = 0; c < 4; c++) yacc[nt][c] = 0.f;
    float m0 = -1e30f, m1 = -1e30f, l0 = 0.f, l1 = 0.f;

    __half* pw0 = sP + (size_t)(16 * warp + g) * QH;
    __half* pw1 = pw0 + 8 * QH;

    for (int kt = 0; kt <= qb; kt++) {
        const int k0 = kt * 128;

        // load K tile
        for (int i = 0; i < 8; i++) {
            int e = tid + i * 256;
            int row = e >> 4;
            int col = (e & 15) * 8;
            *(uint4*)&sKV[row * QH + col] = *(const uint4*)(g_k + bh + (size_t)(k0 + row) * D_ + col);
        }
        __syncthreads();

        // S = Q K^T  (D=128 -> 8 k16 steps)
        float sacc[16][4];
#pragma unroll
        for (int nt = 0; nt < 16; nt++)
#pragma unroll
            for (int c = 0; c < 4; c++) sacc[nt][c] = 0.f;

#pragma unroll
        for (int ks = 0; ks < 8; ks++) {
            uint32_t a[4];
            LDSM_X4(a, qAddr + ks * 32);
#pragma unroll
            for (int p = 0; p < 8; p++) {
                uint32_t bq[4];
                LDSM_X4(bq, kAddr + (uint32_t)(p * 16 * QH * 2) + ks * 32);
                MMA_F16(sacc[2 * p],     a, bq);
                MMA_F16(sacc[2 * p + 1], a, bq + 2);
            }
        }

        // causal mask on diagonal tile
        if (kt == qb) {
            const int r0g = q0 + 16 * warp + g;
            const int r1g = r0g + 8;
#pragma unroll
            for (int nt = 0; nt < 16; nt++) {
                int c0 = k0 + nt * 8 + 2 * tg;
                if (c0     > r0g) sacc[nt][0] = -1e30f;
                if (c0 + 1 > r0g) sacc[nt][1] = -1e30f;
                if (c0     > r1g) sacc[nt][2] = -1e30f;
                if (c0 + 1 > r1g) sacc[nt][3] = -1e30f;
            }
        }

        // online softmax
        float mx0 = -1e30f, mx1 = -1e30f;
#pragma unroll
        for (int nt = 0; nt < 16; nt++) {
            mx0 = fmaxf(mx0, fmaxf(sacc[nt][0], sacc[nt][1]));
            mx1 = fmaxf(mx1, fmaxf(sacc[nt][2], sacc[nt][3]));
        }
        mx0 = fmaxf(mx0, __shfl_xor_sync(0xffffffffu, mx0, 1));
        mx0 = fmaxf(mx0, __shfl_xor_sync(0xffffffffu, mx0, 2));
        mx1 = fmaxf(mx1, __shfl_xor_sync(0xffffffffu, mx1, 1));
        mx1 = fmaxf(mx1, __shfl_xor_sync(0xffffffffu, mx1, 2));

        float nm0 = fmaxf(m0, mx0), nm1 = fmaxf(m1, mx1);
        float cf0 = __expf(m0 - nm0), cf1 = __expf(m1 - nm1);
        m0 = nm0; m1 = nm1;

        float rs0 = 0.f, rs1 = 0.f;
#pragma unroll
        for (int nt = 0; nt < 16; nt++) {
            sacc[nt][0] = __expf(sacc[nt][0] - nm0);
            sacc[nt][1] = __expf(sacc[nt][1] - nm0);
            sacc[nt][2] = __expf(sacc[nt][2] - nm1);
            sacc[nt][3] = __expf(sacc[nt][3] - nm1);
            rs0 += sacc[nt][0] + sacc[nt][1];
            rs1 += sacc[nt][2] + sacc[nt][3];
        }
        rs0 += __shfl_xor_sync(0xffffffffu, rs0, 1);
        rs0 += __shfl_xor_sync(0xffffffffu, rs0, 2);
        rs1 += __shfl_xor_sync(0xffffffffu, rs1, 1);
        rs1 += __shfl_xor_sync(0xffffffffu, rs1, 2);
        l0 = l0 * cf0 + rs0;
        l1 = l1 * cf1 + rs1;

#pragma unroll
        for (int nt = 0; nt < 16; nt++) {
            yacc[nt][0] *= cf0; yacc[nt][1] *= cf0;
            yacc[nt][2] *= cf1; yacc[nt][3] *= cf1;
        }

        // stage P (fp16 RN)
#pragma unroll
        for (int nt = 0; nt < 16; nt++) {
            int col = nt * 8 + 2 * tg;
            *(__half2*)&pw0[col] = __floats2half2_rn(sacc[nt][0], sacc[nt][1]);
            *(__half2*)&pw1[col] = __floats2half2_rn(sacc[nt][2], sacc[nt][3]);
        }
        __syncwarp();
        __syncthreads();

        // load V tile (reuse sKV)
        for (int i = 0; i < 8; i++) {
            int e = tid + i * 256;
            int row = e >> 4;
            int col = (e & 15) * 8;
            *(uint4*)&sKV[row * QH + col] = *(const uint4*)(g_v + bh + (size_t)(k0 + row) * D_ + col);
        }
        __syncthreads();

        // yacc += P V  (keys=128 -> 8 k16 steps; V^T via ldmatrix.trans)
#pragma unroll
        for (int ks = 0; ks < 8; ks++) {
            uint32_t a[4];
            LDSM_X4(a, pAddr + ks * 32);
#pragma unroll
            for (int p = 0; p < 8; p++) {
                uint32_t bq[4];
                LDSM_X4_T(bq, vAddr + (uint32_t)(ks * 16 * QH * 2) + p * 32);
                MMA_F16(yacc[2 * p],     a, bq);
                MMA_F16(yacc[2 * p + 1], a, bq + 2);
            }
        }
        __syncthreads();
    }

    // epilogue: fp16 y (feeds proj GEMM)
    const float inv0 = 1.f / l0;
    const float inv1 = 1.f / l1;
    const int r0g = q0 + 16 * warp + g;
    const int r1g = r0g + 8;
#pragma unroll
    for (int nt = 0; nt < 16; nt++) {
        int col = h * D_ + nt * 8 + 2 * tg;
        *(__half2*)&Y[(size_t)(b * T_ + r0g) * C_ + col] =
            __floats2half2_rn(yacc[nt][0] * inv0, yacc[nt][1] * inv0);
        *(__half2*)&Y[(size_t)(b * T_ + r1g) * C_ + col] =
            __floats2half2_rn(yacc[nt][2] * inv1, yacc[nt][3] * inv1);
    }
}

// ---------------- launch ----------------
extern "C" void kernel_launch(void* const* d_in, const int* in_sizes, int n_in,
                              void* d_out, int out_size)
{
    const float* x     = (const float*)d_in[0];
    const float* Wqkv  = (const float*)d_in[1];
    const float* Wproj = (const float*)d_in[2];
    const float* gain  = (const float*)d_in[3];
    const float* cosb  = (const float*)d_in[4];
    const float* sinb  = (const float*)d_in[5];
    float* out = (float*)d_out;

    float* qkv;
    __half *y, *xh, *wq, *wp;
    cudaGetSymbolAddress((void**)&qkv, g_qkv);
    cudaGetSymbolAddress((void**)&y,   g_y);
    cudaGetSymbolAddress((void**)&xh,  g_xh);
    cudaGetSymbolAddress((void**)&wq,  g_wq);
    cudaGetSymbolAddress((void**)&wp,  g_wp);

    const size_t gemm_smem = (size_t)4 * HS_SZ * sizeof(__half);   // 40960
    cudaFuncSetAttribute(gemm_f16, cudaFuncAttributeMaxDynamicSharedMemorySize, (int)gemm_smem);

    // 0) convert inputs to fp16
    {
        int n8x = (B_ * T_ * C_) / 8;
        cvt_f16_kernel<<<(n8x + 255) / 256, 256>>>((const float4*)x, (uint4*)xh, n8x);
        int n8q = (F_ * C_) / 8;
        cvt_f16_kernel<<<(n8q + 255) / 256, 256>>>((const float4*)Wqkv, (uint4*)wq, n8q);
        int n8p = (C_ * C_) / 8;
        cvt_f16_kernel<<<(n8p + 255) / 256, 256>>>((const float4*)Wproj, (uint4*)wp, n8p);
    }

    // 1) QKV GEMM: [4096,2048] x [6144,2048]^T -> [4096,6144] fp32
    {
        dim3 grid(F_ / 128, (B_ * T_) / 128);
        gemm_f16<<<grid, 256, gemm_smem>>>(xh, wq, qkv, B_ * T_, F_, C_);
    }

    // 2) RoPE + split + gain (emits fp16)
    {
        int total = B_ * T_ * H_ * 64;
        rope_kernel<<<total / 256, 256>>>(gain, cosb, sinb);
    }

    // 3) attention (fp16 tensor core)
    {
        size_t smem = (size_t)3 * 128 * QH * sizeof(__half);   // 104448
        cudaFuncSetAttribute(attn_tc, cudaFuncAttributeMaxDynamicSharedMemorySize, (int)smem);
        dim3 grid(T_ / 128, H_, B_);
        attn_tc<<<grid, 256, smem>>>(y);
    }

    // 4) output projection: [4096,2048] x [2048,2048]^T -> out fp32
    {
        dim3 grid(C_ / 128, (B_ * T_) / 128);
        gemm_f16<<<grid, 256, gemm_smem>>>(y, wp, out, B_ * T_, C_, C_);
    }
}

// round 10
// speedup vs baseline: 1.7743x; 1.0660x over previous
#include <cuda_runtime.h>
#include <cuda_fp16.h>
#include <math.h>
#include <float.h>
#include <stdint.h>

#define B_ 2
#define T_ 2048
#define C_ 2048
#define H_ 16
#define D_ 128
#define F_ (3*C_)

// ---------------- scratch ----------------
__device__ float  g_qkv[(size_t)B_ * T_ * F_];      // raw fp32 GEMM output
__device__ __half g_q[(size_t)B_ * H_ * T_ * D_];   // fp16
__device__ __half g_k[(size_t)B_ * H_ * T_ * D_];
__device__ __half g_v[(size_t)B_ * H_ * T_ * D_];
__device__ __half g_y[(size_t)B_ * T_ * C_];
__device__ __half g_xh[(size_t)B_ * T_ * C_];       // fp16 x
__device__ __half g_wq[(size_t)F_ * C_];            // fp16 Wqkv
__device__ __half g_wp[(size_t)C_ * C_];            // fp16 Wproj

// ---------------- helpers ----------------
#define MMA_F16(c, a, b)                                                      \
  asm volatile(                                                               \
      "mma.sync.aligned.m16n8k16.row.col.f32.f16.f16.f32 "                    \
      "{%0,%1,%2,%3}, {%4,%5,%6,%7}, {%8,%9}, {%0,%1,%2,%3};"                 \
      : "+f"((c)[0]), "+f"((c)[1]), "+f"((c)[2]), "+f"((c)[3])                \
      : "r"((a)[0]), "r"((a)[1]), "r"((a)[2]), "r"((a)[3]),                   \
        "r"((b)[0]), "r"((b)[1]))

#define LDSM_X4(r, addr)                                                      \
  asm volatile("ldmatrix.sync.aligned.m8n8.x4.shared.b16 {%0,%1,%2,%3}, [%4];"\
      : "=r"((r)[0]), "=r"((r)[1]), "=r"((r)[2]), "=r"((r)[3])                \
      : "r"(addr))

#define LDSM_X4_T(r, addr)                                                    \
  asm volatile("ldmatrix.sync.aligned.m8n8.x4.trans.shared.b16 {%0,%1,%2,%3}, [%4];"\
      : "=r"((r)[0]), "=r"((r)[1]), "=r"((r)[2]), "=r"((r)[3])                \
      : "r"(addr))

__device__ __forceinline__ uint32_t smem_u32(const void* p) {
    return (uint32_t)__cvta_generic_to_shared(p);
}
__device__ __forceinline__ void cp16(void* sdst, const void* gsrc) {
    uint32_t s = smem_u32(sdst);
    asm volatile("cp.async.cg.shared.global [%0], [%1], 16;" :: "r"(s), "l"(gsrc));
}
#define CP_COMMIT() asm volatile("cp.async.commit_group;" ::)
#define CP_WAIT1()  asm volatile("cp.async.wait_group 1;" ::)

// ---------------- fp32 -> fp16 convert (8 elems/thread) ----------------
__global__ __launch_bounds__(256) void cvt_f16_kernel(const float4* __restrict__ src,
                                                      uint4* __restrict__ dst, int n8)
{
    int i = blockIdx.x * blockDim.x + threadIdx.x;
    if (i < n8) {
        float4 a = src[2 * i];
        float4 b = src[2 * i + 1];
        __half2 h0 = __floats2half2_rn(a.x, a.y);
        __half2 h1 = __floats2half2_rn(a.z, a.w);
        __half2 h2 = __floats2half2_rn(b.x, b.y);
        __half2 h3 = __floats2half2_rn(b.z, b.w);
        uint4 o = {*(uint32_t*)&h0, *(uint32_t*)&h1, *(uint32_t*)&h2, *(uint32_t*)&h3};
        dst[i] = o;
    }
}

// ---------------- fp16 GEMM: C[m][n] = sum_k A[m][k]*B[n][k] -----------------
// CTA 128x128, 4 warps (2m x 2n), warp tile 64x64, KS=32, 2-stage cp.async.
#define HSTR 40                     // halves per smem row (80B, conflict-free)
#define HS_SZ (128 * HSTR)          // halves per stage per matrix

__global__ __launch_bounds__(128, 2) void gemm_f16(const __half* __restrict__ A,
                                                   const __half* __restrict__ Bm,
                                                   float* __restrict__ Cm,
                                                   int M, int N, int K)
{
    extern __shared__ __half hsm[];
    __half* As = hsm;                // [2][128][HSTR]
    __half* Bs = hsm + 2 * HS_SZ;    // [2][128][HSTR]

    const int tid  = threadIdx.x;
    const int warp = tid >> 5;
    const int lane = tid & 31;
    const int g    = lane >> 2;
    const int tg   = lane & 3;
    const int lm8  = lane & 7;
    const int lq   = lane >> 3;      // 0..3
    const int wm   = (warp >> 1) * 64;
    const int wn   = (warp & 1) * 64;
    const int m0   = blockIdx.y * 128;
    const int n0   = blockIdx.x * 128;

    const uint32_t sbA = smem_u32(As);
    const uint32_t sbB = smem_u32(Bs);
    const uint32_t aBase = sbA + (uint32_t)((wm + lm8 + ((lq & 1) << 3)) * HSTR) * 2
                               + ((uint32_t)(lq >> 1) << 4);
    const uint32_t bBase = sbB + (uint32_t)((wn + lm8 + ((lq >> 1) << 3)) * HSTR) * 2
                               + ((uint32_t)(lq & 1) << 4);
    const uint32_t stageBytes = HS_SZ * 2;

    float acc[4][8][4];
#pragma unroll
    for (int mi = 0; mi < 4; mi++)
#pragma unroll
        for (int ni = 0; ni < 8; ni++)
#pragma unroll
            for (int c = 0; c < 4; c++) acc[mi][ni][c] = 0.f;

    // loader: 1024 16B-chunks per stage (A 512 + B 512) / 128 thr = 8 each
    auto load_stage = [&](int s, int k0) {
#pragma unroll
        for (int t = 0; t < 4; t++) {
            int cid = tid + t * 128;
            int row = cid >> 2;
            int ch8 = (cid & 3) * 8;
            cp16(&As[(size_t)s * HS_SZ + row * HSTR + ch8],
                 A + (size_t)(m0 + row) * K + k0 + ch8);
            cp16(&Bs[(size_t)s * HS_SZ + row * HSTR + ch8],
                 Bm + (size_t)(n0 + row) * K + k0 + ch8);
        }
    };

    load_stage(0, 0);  CP_COMMIT();
    load_stage(1, 32); CP_COMMIT();
    CP_WAIT1();
    __syncthreads();

    const int nK = K / 32;
    int cur = 0;
    for (int kt = 0; kt < nK; kt++) {
        const uint32_t sOff = (uint32_t)cur * stageBytes;
#pragma unroll
        for (int ks = 0; ks < 2; ks++) {      // two k16 steps
            uint32_t af[4][4], bq[4][4];
#pragma unroll
            for (int mi = 0; mi < 4; mi++)
                LDSM_X4(af[mi], aBase + sOff + (uint32_t)(mi * 16 * HSTR * 2) + ks * 32);
#pragma unroll
            for (int p = 0; p < 4; p++)
                LDSM_X4(bq[p], bBase + sOff + (uint32_t)(p * 16 * HSTR * 2) + ks * 32);
#pragma unroll
            for (int mi = 0; mi < 4; mi++)
#pragma unroll
                for (int p = 0; p < 4; p++) {
                    MMA_F16(acc[mi][2 * p],     af[mi], bq[p]);
                    MMA_F16(acc[mi][2 * p + 1], af[mi], bq[p] + 2);
                }
        }
        __syncthreads();
        if (kt + 2 < nK) load_stage(cur, (kt + 2) * 32);
        CP_COMMIT();
        CP_WAIT1();
        __syncthreads();
        cur ^= 1;
    }

#pragma unroll
    for (int mi = 0; mi < 4; mi++) {
#pragma unroll
        for (int ni = 0; ni < 8; ni++) {
            const int r = m0 + wm + mi * 16 + g;
            const int c = n0 + wn + ni * 8 + 2 * tg;
            float2 v0 = {acc[mi][ni][0], acc[mi][ni][1]};
            float2 v1 = {acc[mi][ni][2], acc[mi][ni][3]};
            *(float2*)&Cm[(size_t)r * N + c]       = v0;
            *(float2*)&Cm[(size_t)(r + 8) * N + c] = v1;
        }
    }
}

// ---------------- RoPE + split + gain-fold (emits fp16 q/k/v) ----------------
__global__ __launch_bounds__(256) void rope_kernel(const float* __restrict__ gain,
                                                   const float* __restrict__ cosb,
                                                   const float* __restrict__ sinb)
{
    int idx = blockIdx.x * blockDim.x + threadIdx.x;
    int d = idx & 63;
    int h = (idx >> 6) & 15;
    int t = (idx >> 10) & 2047;
    int b = idx >> 21;

    size_t base = ((size_t)(b * T_ + t)) * F_ + h * D_;
    float c = cosb[t * 64 + d];
    float s = sinb[t * 64 + d];

    float q1 = g_qkv[base + d],            q2 = g_qkv[base + d + 64];
    float k1 = g_qkv[base + C_ + d],       k2 = g_qkv[base + C_ + d + 64];
    float v1 = g_qkv[base + 2 * C_ + d],   v2 = g_qkv[base + 2 * C_ + d + 64];

    float gn = gain[h] * rsqrtf((float)D_);
    size_t ob = ((size_t)((b * H_ + h) * T_ + t)) * D_;

    g_q[ob + d]      = __float2half_rn((q1 * c - q2 * s) * gn);
    g_q[ob + d + 64] = __float2half_rn((q2 * c + q1 * s) * gn);
    g_k[ob + d]      = __float2half_rn(k1 * c - k2 * s);
    g_k[ob + d + 64] = __float2half_rn(k2 * c + k1 * s);
    g_v[ob + d]      = __float2half_rn(v1);
    g_v[ob + d + 64] = __float2half_rn(v2);
}

// ---------------- fp16 tensor-core causal flash attention --------------------
#define QH 136    // halves per row (272B stride, conflict-free)

__global__ __launch_bounds__(256, 1) void attn_tc(__half* __restrict__ Y)
{
    extern __shared__ __half ham[];
    __half* sQ  = ham;                       // [128][QH]
    __half* sKV = ham + 128 * QH;            // [128][QH] (K then V)
    __half* sP  = sKV + 128 * QH;            // [128][QH]

    const int tid  = threadIdx.x;
    const int warp = tid >> 5;
    const int lane = tid & 31;
    const int g    = lane >> 2;
    const int tg   = lane & 3;
    const int lm8  = lane & 7;
    const int lq   = lane >> 3;
    const int qb = blockIdx.x;
    const int h  = blockIdx.y;
    const int b  = blockIdx.z;
    const int q0 = qb * 128;
    const size_t bh = ((size_t)(b * H_ + h)) * T_ * D_;

    const uint32_t qAddr = smem_u32(sQ)
        + (uint32_t)((16 * warp + lm8 + ((lq & 1) << 3)) * QH) * 2
        + ((uint32_t)(lq >> 1) << 4);
    const uint32_t kAddr = smem_u32(sKV)
        + (uint32_t)((lm8 + ((lq >> 1) << 3)) * QH) * 2
        + ((uint32_t)(lq & 1) << 4);
    const uint32_t vAddr = smem_u32(sKV)
        + (uint32_t)((lm8 + ((lq & 1) << 3)) * QH) * 2
        + ((uint32_t)(lq >> 1) << 4);
    const uint32_t pAddr = smem_u32(sP)
        + (uint32_t)((16 * warp + lm8 + ((lq & 1) << 3)) * QH) * 2
        + ((uint32_t)(lq >> 1) << 4);

    // load Q tile: 128 rows x 16 uint4 = 2048 -> 8/thread
    for (int i = 0; i < 8; i++) {
        int e = tid + i * 256;
        int row = e >> 4;
        int col = (e & 15) * 8;
        *(uint4*)&sQ[row * QH + col] = *(const uint4*)(g_q + bh + (size_t)(q0 + row) * D_ + col);
    }

    float yacc[16][4];
#pragma unroll
    for (int nt = 0; nt < 16; nt++)
#pragma unroll
        for (int c = 0; c < 4; c++) yacc[nt][c] = 0.f;
    float m0 = -1e30f, m1 = -1e30f, l0 = 0.f, l1 = 0.f;

    __half* pw0 = sP + (size_t)(16 * warp + g) * QH;
    __half* pw1 = pw0 + 8 * QH;

    for (int kt = 0; kt <= qb; kt++) {
        const int k0 = kt * 128;

        // load K tile
        for (int i = 0; i < 8; i++) {
            int e = tid + i * 256;
            int row = e >> 4;
            int col = (e & 15) * 8;
            *(uint4*)&sKV[row * QH + col] = *(const uint4*)(g_k + bh + (size_t)(k0 + row) * D_ + col);
        }
        __syncthreads();

        // S = Q K^T  (D=128 -> 8 k16 steps)
        float sacc[16][4];
#pragma unroll
        for (int nt = 0; nt < 16; nt++)
#pragma unroll
            for (int c = 0; c < 4; c++) sacc[nt][c] = 0.f;

#pragma unroll
        for (int ks = 0; ks < 8; ks++) {
            uint32_t a[4];
            LDSM_X4(a, qAddr + ks * 32);
#pragma unroll
            for (int p = 0; p < 8; p++) {
                uint32_t bq[4];
                LDSM_X4(bq, kAddr + (uint32_t)(p * 16 * QH * 2) + ks * 32);
                MMA_F16(sacc[2 * p],     a, bq);
                MMA_F16(sacc[2 * p + 1], a, bq + 2);
            }
        }

        // causal mask on diagonal tile
        if (kt == qb) {
            const int r0g = q0 + 16 * warp + g;
            const int r1g = r0g + 8;
#pragma unroll
            for (int nt = 0; nt < 16; nt++) {
                int c0 = k0 + nt * 8 + 2 * tg;
                if (c0     > r0g) sacc[nt][0] = -1e30f;
                if (c0 + 1 > r0g) sacc[nt][1] = -1e30f;
                if (c0     > r1g) sacc[nt][2] = -1e30f;
                if (c0 + 1 > r1g) sacc[nt][3] = -1e30f;
            }
        }

        // online softmax
        float mx0 = -1e30f, mx1 = -1e30f;
#pragma unroll
        for (int nt = 0; nt < 16; nt++) {
            mx0 = fmaxf(mx0, fmaxf(sacc[nt][0], sacc[nt][1]));
            mx1 = fmaxf(mx1, fmaxf(sacc[nt][2], sacc[nt][3]));
        }
        mx0 = fmaxf(mx0, __shfl_xor_sync(0xffffffffu, mx0, 1));
        mx0 = fmaxf(mx0, __shfl_xor_sync(0xffffffffu, mx0, 2));
        mx1 = fmaxf(mx1, __shfl_xor_sync(0xffffffffu, mx1, 1));
        mx1 = fmaxf(mx1, __shfl_xor_sync(0xffffffffu, mx1, 2));

        float nm0 = fmaxf(m0, mx0), nm1 = fmaxf(m1, mx1);
        float cf0 = __expf(m0 - nm0), cf1 = __expf(m1 - nm1);
        m0 = nm0; m1 = nm1;

        float rs0 = 0.f, rs1 = 0.f;
#pragma unroll
        for (int nt = 0; nt < 16; nt++) {
            sacc[nt][0] = __expf(sacc[nt][0] - nm0);
            sacc[nt][1] = __expf(sacc[nt][1] - nm0);
            sacc[nt][2] = __expf(sacc[nt][2] - nm1);
            sacc[nt][3] = __expf(sacc[nt][3] - nm1);
            rs0 += sacc[nt][0] + sacc[nt][1];
            rs1 += sacc[nt][2] + sacc[nt][3];
        }
        rs0 += __shfl_xor_sync(0xffffffffu, rs0, 1);
        rs0 += __shfl_xor_sync(0xffffffffu, rs0, 2);
        rs1 += __shfl_xor_sync(0xffffffffu, rs1, 1);
        rs1 += __shfl_xor_sync(0xffffffffu, rs1, 2);
        l0 = l0 * cf0 + rs0;
        l1 = l1 * cf1 + rs1;

#pragma unroll
        for (int nt = 0; nt < 16; nt++) {
            yacc[nt][0] *= cf0; yacc[nt][1] *= cf0;
            yacc[nt][2] *= cf1; yacc[nt][3] *= cf1;
        }

        // stage P (fp16 RN)
#pragma unroll
        for (int nt = 0; nt < 16; nt++) {
            int col = nt * 8 + 2 * tg;
            *(__half2*)&pw0[col] = __floats2half2_rn(sacc[nt][0], sacc[nt][1]);
            *(__half2*)&pw1[col] = __floats2half2_rn(sacc[nt][2], sacc[nt][3]);
        }
        __syncwarp();
        __syncthreads();

        // load V tile (reuse sKV)
        for (int i = 0; i < 8; i++) {
            int e = tid + i * 256;
            int row = e >> 4;
            int col = (e & 15) * 8;
            *(uint4*)&sKV[row * QH + col] = *(const uint4*)(g_v + bh + (size_t)(k0 + row) * D_ + col);
        }
        __syncthreads();

        // yacc += P V  (keys=128 -> 8 k16 steps; V^T via ldmatrix.trans)
#pragma unroll
        for (int ks = 0; ks < 8; ks++) {
            uint32_t a[4];
            LDSM_X4(a, pAddr + ks * 32);
#pragma unroll
            for (int p = 0; p < 8; p++) {
                uint32_t bq[4];
                LDSM_X4_T(bq, vAddr + (uint32_t)(ks * 16 * QH * 2) + p * 32);
                MMA_F16(yacc[2 * p],     a, bq);
                MMA_F16(yacc[2 * p + 1], a, bq + 2);
            }
        }
        __syncthreads();
    }

    // epilogue: fp16 y (feeds proj GEMM)
    const float inv0 = 1.f / l0;
    const float inv1 = 1.f / l1;
    const int r0g = q0 + 16 * warp + g;
    const int r1g = r0g + 8;
#pragma unroll
    for (int nt = 0; nt < 16; nt++) {
        int col = h * D_ + nt * 8 + 2 * tg;
        *(__half2*)&Y[(size_t)(b * T_ + r0g) * C_ + col] =
            __floats2half2_rn(yacc[nt][0] * inv0, yacc[nt][1] * inv0);
        *(__half2*)&Y[(size_t)(b * T_ + r1g) * C_ + col] =
            __floats2half2_rn(yacc[nt][2] * inv1, yacc[nt][3] * inv1);
    }
}

// ---------------- launch ----------------
extern "C" void kernel_launch(void* const* d_in, const int* in_sizes, int n_in,
                              void* d_out, int out_size)
{
    const float* x     = (const float*)d_in[0];
    const float* Wqkv  = (const float*)d_in[1];
    const float* Wproj = (const float*)d_in[2];
    const float* gain  = (const float*)d_in[3];
    const float* cosb  = (const float*)d_in[4];
    const float* sinb  = (const float*)d_in[5];
    float* out = (float*)d_out;

    float* qkv;
    __half *y, *xh, *wq, *wp;
    cudaGetSymbolAddress((void**)&qkv, g_qkv);
    cudaGetSymbolAddress((void**)&y,   g_y);
    cudaGetSymbolAddress((void**)&xh,  g_xh);
    cudaGetSymbolAddress((void**)&wq,  g_wq);
    cudaGetSymbolAddress((void**)&wp,  g_wp);

    const size_t gemm_smem = (size_t)4 * HS_SZ * sizeof(__half);   // 40960
    cudaFuncSetAttribute(gemm_f16, cudaFuncAttributeMaxDynamicSharedMemorySize, (int)gemm_smem);

    // 0) convert inputs to fp16
    {
        int n8x = (B_ * T_ * C_) / 8;
        cvt_f16_kernel<<<(n8x + 255) / 256, 256>>>((const float4*)x, (uint4*)xh, n8x);
        int n8q = (F_ * C_) / 8;
        cvt_f16_kernel<<<(n8q + 255) / 256, 256>>>((const float4*)Wqkv, (uint4*)wq, n8q);
        int n8p = (C_ * C_) / 8;
        cvt_f16_kernel<<<(n8p + 255) / 256, 256>>>((const float4*)Wproj, (uint4*)wp, n8p);
    }

    // 1) QKV GEMM: [4096,2048] x [6144,2048]^T -> [4096,6144] fp32
    {
        dim3 grid(F_ / 128, (B_ * T_) / 128);
        gemm_f16<<<grid, 128, gemm_smem>>>(xh, wq, qkv, B_ * T_, F_, C_);
    }

    // 2) RoPE + split + gain (emits fp16)
    {
        int total = B_ * T_ * H_ * 64;
        rope_kernel<<<total / 256, 256>>>(gain, cosb, sinb);
    }

    // 3) attention (fp16 tensor core)
    {
        size_t smem = (size_t)3 * 128 * QH * sizeof(__half);   // 104448
        cudaFuncSetAttribute(attn_tc, cudaFuncAttributeMaxDynamicSharedMemorySize, (int)smem);
        dim3 grid(T_ / 128, H_, B_);
        attn_tc<<<grid, 256, smem>>>(y);
    }

    // 4) output projection: [4096,2048] x [2048,2048]^T -> out fp32
    {
        dim3 grid(C_ / 128, (B_ * T_) / 128);
        gemm_f16<<<grid, 128, gemm_smem>>>(y, wp, out, B_ * T_, C_, C_);
    }
}

// round 11
// speedup vs baseline: 1.9728x; 1.1119x over previous
#include <cuda_runtime.h>
#include <cuda_fp16.h>
#include <math.h>
#include <float.h>
#include <stdint.h>

#define B_ 2
#define T_ 2048
#define C_ 2048
#define H_ 16
#define D_ 128
#define F_ (3*C_)

// ---------------- scratch ----------------
__device__ float  g_qkv[(size_t)B_ * T_ * F_];      // raw fp32 GEMM output
__device__ __half g_q[(size_t)B_ * H_ * T_ * D_];   // fp16
__device__ __half g_k[(size_t)B_ * H_ * T_ * D_];
__device__ __half g_v[(size_t)B_ * H_ * T_ * D_];
__device__ __half g_y[(size_t)B_ * T_ * C_];
__device__ __half g_xh[(size_t)B_ * T_ * C_];       // fp16 x
__device__ __half g_wq[(size_t)F_ * C_];            // fp16 Wqkv
__device__ __half g_wp[(size_t)C_ * C_];            // fp16 Wproj

// ---------------- helpers ----------------
#define MMA_F16(c, a, b)                                                      \
  asm volatile(                                                               \
      "mma.sync.aligned.m16n8k16.row.col.f32.f16.f16.f32 "                    \
      "{%0,%1,%2,%3}, {%4,%5,%6,%7}, {%8,%9}, {%0,%1,%2,%3};"                 \
      : "+f"((c)[0]), "+f"((c)[1]), "+f"((c)[2]), "+f"((c)[3])                \
      : "r"((a)[0]), "r"((a)[1]), "r"((a)[2]), "r"((a)[3]),                   \
        "r"((b)[0]), "r"((b)[1]))

#define LDSM_X4(r, addr)                                                      \
  asm volatile("ldmatrix.sync.aligned.m8n8.x4.shared.b16 {%0,%1,%2,%3}, [%4];"\
      : "=r"((r)[0]), "=r"((r)[1]), "=r"((r)[2]), "=r"((r)[3])                \
      : "r"(addr))

#define LDSM_X4_T(r, addr)                                                    \
  asm volatile("ldmatrix.sync.aligned.m8n8.x4.trans.shared.b16 {%0,%1,%2,%3}, [%4];"\
      : "=r"((r)[0]), "=r"((r)[1]), "=r"((r)[2]), "=r"((r)[3])                \
      : "r"(addr))

__device__ __forceinline__ uint32_t smem_u32(const void* p) {
    return (uint32_t)__cvta_generic_to_shared(p);
}
__device__ __forceinline__ void cp16(void* sdst, const void* gsrc) {
    uint32_t s = smem_u32(sdst);
    asm volatile("cp.async.cg.shared.global [%0], [%1], 16;" :: "r"(s), "l"(gsrc));
}
#define CP_COMMIT() asm volatile("cp.async.commit_group;" ::)
#define CP_WAIT1()  asm volatile("cp.async.wait_group 1;" ::)

// ---------------- fp32 -> fp16 convert (8 elems/thread) ----------------
__global__ __launch_bounds__(256) void cvt_f16_kernel(const float4* __restrict__ src,
                                                      uint4* __restrict__ dst, int n8)
{
    int i = blockIdx.x * blockDim.x + threadIdx.x;
    if (i < n8) {
        float4 a = src[2 * i];
        float4 b = src[2 * i + 1];
        __half2 h0 = __floats2half2_rn(a.x, a.y);
        __half2 h1 = __floats2half2_rn(a.z, a.w);
        __half2 h2 = __floats2half2_rn(b.x, b.y);
        __half2 h3 = __floats2half2_rn(b.z, b.w);
        uint4 o = {*(uint32_t*)&h0, *(uint32_t*)&h1, *(uint32_t*)&h2, *(uint32_t*)&h3};
        dst[i] = o;
    }
}

// ---------------- fp16 GEMM: C[m][n] = sum_k A[m][k]*B[n][k] -----------------
// CTA 128x128, 4 warps (2m x 2n), warp tile 64x64, KS=64, 2-stage cp.async,
// register double-buffered fragments (LDSM of ks+1 overlaps MMA of ks).
#define HSTR 72                     // halves per smem row (144B, conflict-free)
#define HS_SZ (128 * HSTR)          // halves per stage per matrix

__global__ __launch_bounds__(128, 2) void gemm_f16(const __half* __restrict__ A,
                                                   const __half* __restrict__ Bm,
                                                   float* __restrict__ Cm,
                                                   int M, int N, int K)
{
    extern __shared__ __half hsm[];
    __half* As = hsm;                // [2][128][HSTR]
    __half* Bs = hsm + 2 * HS_SZ;    // [2][128][HSTR]

    const int tid  = threadIdx.x;
    const int warp = tid >> 5;
    const int lane = tid & 31;
    const int g    = lane >> 2;
    const int tg   = lane & 3;
    const int lm8  = lane & 7;
    const int lq   = lane >> 3;      // 0..3
    const int wm   = (warp >> 1) * 64;
    const int wn   = (warp & 1) * 64;
    const int m0   = blockIdx.y * 128;
    const int n0   = blockIdx.x * 128;

    const uint32_t sbA = smem_u32(As);
    const uint32_t sbB = smem_u32(Bs);
    const uint32_t aBase = sbA + (uint32_t)((wm + lm8 + ((lq & 1) << 3)) * HSTR) * 2
                               + ((uint32_t)(lq >> 1) << 4);
    const uint32_t bBase = sbB + (uint32_t)((wn + lm8 + ((lq >> 1) << 3)) * HSTR) * 2
                               + ((uint32_t)(lq & 1) << 4);
    const uint32_t stageBytes = HS_SZ * 2;

    float acc[4][8][4];
#pragma unroll
    for (int mi = 0; mi < 4; mi++)
#pragma unroll
        for (int ni = 0; ni < 8; ni++)
#pragma unroll
            for (int c = 0; c < 4; c++) acc[mi][ni][c] = 0.f;

    // fragment double-buffer
    uint32_t af[2][4][4], bq[2][4][4];

    // loader: 128 rows x 8 16B-chunks per matrix = 2048 chunks -> 16/thread
    auto load_stage = [&](int s, int k0) {
#pragma unroll
        for (int t = 0; t < 8; t++) {
            int cid = tid + t * 128;
            int row = cid >> 3;
            int ch8 = (cid & 7) * 8;
            cp16(&As[(size_t)s * HS_SZ + row * HSTR + ch8],
                 A + (size_t)(m0 + row) * K + k0 + ch8);
            cp16(&Bs[(size_t)s * HS_SZ + row * HSTR + ch8],
                 Bm + (size_t)(n0 + row) * K + k0 + ch8);
        }
    };

#define LD_FRAG(buf, sOff, ks)                                                  \
    do {                                                                        \
        _Pragma("unroll")                                                       \
        for (int mi = 0; mi < 4; mi++)                                          \
            LDSM_X4(af[buf][mi], aBase + (sOff) + (uint32_t)(mi * 16 * HSTR * 2) + (ks) * 32); \
        _Pragma("unroll")                                                       \
        for (int p = 0; p < 4; p++)                                             \
            LDSM_X4(bq[buf][p], bBase + (sOff) + (uint32_t)(p * 16 * HSTR * 2) + (ks) * 32);   \
    } while (0)

#define DO_MMA(buf)                                                             \
    do {                                                                        \
        _Pragma("unroll")                                                       \
        for (int mi = 0; mi < 4; mi++)                                          \
            _Pragma("unroll")                                                   \
            for (int p = 0; p < 4; p++) {                                       \
                MMA_F16(acc[mi][2 * p],     af[buf][mi], bq[buf][p]);           \
                MMA_F16(acc[mi][2 * p + 1], af[buf][mi], bq[buf][p] + 2);       \
            }                                                                   \
    } while (0)

    load_stage(0, 0);  CP_COMMIT();
    load_stage(1, 64); CP_COMMIT();
    CP_WAIT1();
    __syncthreads();

    const int nK = K / 64;
    int cur = 0;
    LD_FRAG(0, 0u, 0);                       // prefetch first fragments

    for (int kt = 0; kt < nK; kt++) {
        const uint32_t sOff = (uint32_t)cur * stageBytes;
#pragma unroll
        for (int ks = 0; ks < 4; ks++) {
            const int cb = ks & 1;
            if (ks < 3) {
                if (cb) LD_FRAG(0, sOff, ks + 1);
                else    LD_FRAG(1, sOff, ks + 1);
            }
            if (cb) DO_MMA(1); else DO_MMA(0);
        }
        __syncthreads();                      // done reading cur stage
        if (kt + 2 < nK) load_stage(cur, (kt + 2) * 64);
        CP_COMMIT();
        CP_WAIT1();                           // next stage ready
        __syncthreads();
        cur ^= 1;
        if (kt + 1 < nK)
            LD_FRAG(0, (uint32_t)cur * stageBytes, 0);   // prefetch next iter
    }

#pragma unroll
    for (int mi = 0; mi < 4; mi++) {
#pragma unroll
        for (int ni = 0; ni < 8; ni++) {
            const int r = m0 + wm + mi * 16 + g;
            const int c = n0 + wn + ni * 8 + 2 * tg;
            float2 v0 = {acc[mi][ni][0], acc[mi][ni][1]};
            float2 v1 = {acc[mi][ni][2], acc[mi][ni][3]};
            *(float2*)&Cm[(size_t)r * N + c]       = v0;
            *(float2*)&Cm[(size_t)(r + 8) * N + c] = v1;
        }
    }
#undef LD_FRAG
#undef DO_MMA
}

// ---------------- RoPE + split + gain-fold (emits fp16 q/k/v) ----------------
__global__ __launch_bounds__(256) void rope_kernel(const float* __restrict__ gain,
                                                   const float* __restrict__ cosb,
                                                   const float* __restrict__ sinb)
{
    int idx = blockIdx.x * blockDim.x + threadIdx.x;
    int d = idx & 63;
    int h = (idx >> 6) & 15;
    int t = (idx >> 10) & 2047;
    int b = idx >> 21;

    size_t base = ((size_t)(b * T_ + t)) * F_ + h * D_;
    float c = cosb[t * 64 + d];
    float s = sinb[t * 64 + d];

    float q1 = g_qkv[base + d],            q2 = g_qkv[base + d + 64];
    float k1 = g_qkv[base + C_ + d],       k2 = g_qkv[base + C_ + d + 64];
    float v1 = g_qkv[base + 2 * C_ + d],   v2 = g_qkv[base + 2 * C_ + d + 64];

    float gn = gain[h] * rsqrtf((float)D_);
    size_t ob = ((size_t)((b * H_ + h) * T_ + t)) * D_;

    g_q[ob + d]      = __float2half_rn((q1 * c - q2 * s) * gn);
    g_q[ob + d + 64] = __float2half_rn((q2 * c + q1 * s) * gn);
    g_k[ob + d]      = __float2half_rn(k1 * c - k2 * s);
    g_k[ob + d + 64] = __float2half_rn(k2 * c + k1 * s);
    g_v[ob + d]      = __float2half_rn(v1);
    g_v[ob + d + 64] = __float2half_rn(v2);
}

// ---------------- fp16 tensor-core causal flash attention --------------------
#define QH 136    // halves per row (272B stride, conflict-free)

__global__ __launch_bounds__(256, 1) void attn_tc(__half* __restrict__ Y)
{
    extern __shared__ __half ham[];
    __half* sQ  = ham;                       // [128][QH]
    __half* sKV = ham + 128 * QH;            // [128][QH] (K then V)
    __half* sP  = sKV + 128 * QH;            // [128][QH]

    const int tid  = threadIdx.x;
    const int warp = tid >> 5;
    const int lane = tid & 31;
    const int g    = lane >> 2;
    const int tg   = lane & 3;
    const int lm8  = lane & 7;
    const int lq   = lane >> 3;
    const int qb = blockIdx.x;
    const int h  = blockIdx.y;
    const int b  = blockIdx.z;
    const int q0 = qb * 128;
    const size_t bh = ((size_t)(b * H_ + h)) * T_ * D_;

    const uint32_t qAddr = smem_u32(sQ)
        + (uint32_t)((16 * warp + lm8 + ((lq & 1) << 3)) * QH) * 2
        + ((uint32_t)(lq >> 1) << 4);
    const uint32_t kAddr = smem_u32(sKV)
        + (uint32_t)((lm8 + ((lq >> 1) << 3)) * QH) * 2
        + ((uint32_t)(lq & 1) << 4);
    const uint32_t vAddr = smem_u32(sKV)
        + (uint32_t)((lm8 + ((lq & 1) << 3)) * QH) * 2
        + ((uint32_t)(lq >> 1) << 4);
    const uint32_t pAddr = smem_u32(sP)
        + (uint32_t)((16 * warp + lm8 + ((lq & 1) << 3)) * QH) * 2
        + ((uint32_t)(lq >> 1) << 4);

    // load Q tile: 128 rows x 16 uint4 = 2048 -> 8/thread
    for (int i = 0; i < 8; i++) {
        int e = tid + i * 256;
        int row = e >> 4;
        int col = (e & 15) * 8;
        *(uint4*)&sQ[row * QH + col] = *(const uint4*)(g_q + bh + (size_t)(q0 + row) * D_ + col);
    }

    float yacc[16][4];
#pragma unroll
    for (int nt = 0; nt < 16; nt++)
#pragma unroll
        for (int c = 0; c < 4; c++) yacc[nt][c] = 0.f;
    float m0 = -1e30f, m1 = -1e30f, l0 = 0.f, l1 = 0.f;

    __half* pw0 = sP + (size_t)(16 * warp + g) * QH;
    __half* pw1 = pw0 + 8 * QH;

    for (int kt = 0; kt <= qb; kt++) {
        const int k0 = kt * 128;

        // load K tile
        for (int i = 0; i < 8; i++) {
            int e = tid + i * 256;
            int row = e >> 4;
            int col = (e & 15) * 8;
            *(uint4*)&sKV[row * QH + col] = *(const uint4*)(g_k + bh + (size_t)(k0 + row) * D_ + col);
        }
        __syncthreads();

        // S = Q K^T  (D=128 -> 8 k16 steps)
        float sacc[16][4];
#pragma unroll
        for (int nt = 0; nt < 16; nt++)
#pragma unroll
            for (int c = 0; c < 4; c++) sacc[nt][c] = 0.f;

#pragma unroll
        for (int ks = 0; ks < 8; ks++) {
            uint32_t a[4];
            LDSM_X4(a, qAddr + ks * 32);
#pragma unroll
            for (int p = 0; p < 8; p++) {
                uint32_t bqv[4];
                LDSM_X4(bqv, kAddr + (uint32_t)(p * 16 * QH * 2) + ks * 32);
                MMA_F16(sacc[2 * p],     a, bqv);
                MMA_F16(sacc[2 * p + 1], a, bqv + 2);
            }
        }

        // causal mask on diagonal tile
        if (kt == qb) {
            const int r0g = q0 + 16 * warp + g;
            const int r1g = r0g + 8;
#pragma unroll
            for (int nt = 0; nt < 16; nt++) {
                int c0 = k0 + nt * 8 + 2 * tg;
                if (c0     > r0g) sacc[nt][0] = -1e30f;
                if (c0 + 1 > r0g) sacc[nt][1] = -1e30f;
                if (c0     > r1g) sacc[nt][2] = -1e30f;
                if (c0 + 1 > r1g) sacc[nt][3] = -1e30f;
            }
        }

        // online softmax
        float mx0 = -1e30f, mx1 = -1e30f;
#pragma unroll
        for (int nt = 0; nt < 16; nt++) {
            mx0 = fmaxf(mx0, fmaxf(sacc[nt][0], sacc[nt][1]));
            mx1 = fmaxf(mx1, fmaxf(sacc[nt][2], sacc[nt][3]));
        }
        mx0 = fmaxf(mx0, __shfl_xor_sync(0xffffffffu, mx0, 1));
        mx0 = fmaxf(mx0, __shfl_xor_sync(0xffffffffu, mx0, 2));
        mx1 = fmaxf(mx1, __shfl_xor_sync(0xffffffffu, mx1, 1));
        mx1 = fmaxf(mx1, __shfl_xor_sync(0xffffffffu, mx1, 2));

        float nm0 = fmaxf(m0, mx0), nm1 = fmaxf(m1, mx1);
        float cf0 = __expf(m0 - nm0), cf1 = __expf(m1 - nm1);
        m0 = nm0; m1 = nm1;

        float rs0 = 0.f, rs1 = 0.f;
#pragma unroll
        for (int nt = 0; nt < 16; nt++) {
            sacc[nt][0] = __expf(sacc[nt][0] - nm0);
            sacc[nt][1] = __expf(sacc[nt][1] - nm0);
            sacc[nt][2] = __expf(sacc[nt][2] - nm1);
            sacc[nt][3] = __expf(sacc[nt][3] - nm1);
            rs0 += sacc[nt][0] + sacc[nt][1];
            rs1 += sacc[nt][2] + sacc[nt][3];
        }
        rs0 += __shfl_xor_sync(0xffffffffu, rs0, 1);
        rs0 += __shfl_xor_sync(0xffffffffu, rs0, 2);
        rs1 += __shfl_xor_sync(0xffffffffu, rs1, 1);
        rs1 += __shfl_xor_sync(0xffffffffu, rs1, 2);
        l0 = l0 * cf0 + rs0;
        l1 = l1 * cf1 + rs1;

#pragma unroll
        for (int nt = 0; nt < 16; nt++) {
            yacc[nt][0] *= cf0; yacc[nt][1] *= cf0;
            yacc[nt][2] *= cf1; yacc[nt][3] *= cf1;
        }

        // stage P (fp16 RN)
#pragma unroll
        for (int nt = 0; nt < 16; nt++) {
            int col = nt * 8 + 2 * tg;
            *(__half2*)&pw0[col] = __floats2half2_rn(sacc[nt][0], sacc[nt][1]);
            *(__half2*)&pw1[col] = __floats2half2_rn(sacc[nt][2], sacc[nt][3]);
        }
        __syncwarp();
        __syncthreads();

        // load V tile (reuse sKV)
        for (int i = 0; i < 8; i++) {
            int e = tid + i * 256;
            int row = e >> 4;
            int col = (e & 15) * 8;
            *(uint4*)&sKV[row * QH + col] = *(const uint4*)(g_v + bh + (size_t)(k0 + row) * D_ + col);
        }
        __syncthreads();

        // yacc += P V  (keys=128 -> 8 k16 steps; V^T via ldmatrix.trans)
#pragma unroll
        for (int ks = 0; ks < 8; ks++) {
            uint32_t a[4];
            LDSM_X4(a, pAddr + ks * 32);
#pragma unroll
            for (int p = 0; p < 8; p++) {
                uint32_t bqv[4];
                LDSM_X4_T(bqv, vAddr + (uint32_t)(ks * 16 * QH * 2) + p * 32);
                MMA_F16(yacc[2 * p],     a, bqv);
                MMA_F16(yacc[2 * p + 1], a, bqv + 2);
            }
        }
        __syncthreads();
    }

    // epilogue: fp16 y (feeds proj GEMM)
    const float inv0 = 1.f / l0;
    const float inv1 = 1.f / l1;
    const int r0g = q0 + 16 * warp + g;
    const int r1g = r0g + 8;
#pragma unroll
    for (int nt = 0; nt < 16; nt++) {
        int col = h * D_ + nt * 8 + 2 * tg;
        *(__half2*)&Y[(size_t)(b * T_ + r0g) * C_ + col] =
            __floats2half2_rn(yacc[nt][0] * inv0, yacc[nt][1] * inv0);
        *(__half2*)&Y[(size_t)(b * T_ + r1g) * C_ + col] =
            __floats2half2_rn(yacc[nt][2] * inv1, yacc[nt][3] * inv1);
    }
}

// ---------------- launch ----------------
extern "C" void kernel_launch(void* const* d_in, const int* in_sizes, int n_in,
                              void* d_out, int out_size)
{
    const float* x     = (const float*)d_in[0];
    const float* Wqkv  = (const float*)d_in[1];
    const float* Wproj = (const float*)d_in[2];
    const float* gain  = (const float*)d_in[3];
    const float* cosb  = (const float*)d_in[4];
    const float* sinb  = (const float*)d_in[5];
    float* out = (float*)d_out;

    float* qkv;
    __half *y, *xh, *wq, *wp;
    cudaGetSymbolAddress((void**)&qkv, g_qkv);
    cudaGetSymbolAddress((void**)&y,   g_y);
    cudaGetSymbolAddress((void**)&xh,  g_xh);
    cudaGetSymbolAddress((void**)&wq,  g_wq);
    cudaGetSymbolAddress((void**)&wp,  g_wp);

    const size_t gemm_smem = (size_t)4 * HS_SZ * sizeof(__half);   // 73728
    cudaFuncSetAttribute(gemm_f16, cudaFuncAttributeMaxDynamicSharedMemorySize, (int)gemm_smem);

    // 0) convert inputs to fp16
    {
        int n8x = (B_ * T_ * C_) / 8;
        cvt_f16_kernel<<<(n8x + 255) / 256, 256>>>((const float4*)x, (uint4*)xh, n8x);
        int n8q = (F_ * C_) / 8;
        cvt_f16_kernel<<<(n8q + 255) / 256, 256>>>((const float4*)Wqkv, (uint4*)wq, n8q);
        int n8p = (C_ * C_) / 8;
        cvt_f16_kernel<<<(n8p + 255) / 256, 256>>>((const float4*)Wproj, (uint4*)wp, n8p);
    }

    // 1) QKV GEMM: [4096,2048] x [6144,2048]^T -> [4096,6144] fp32
    {
        dim3 grid(F_ / 128, (B_ * T_) / 128);
        gemm_f16<<<grid, 128, gemm_smem>>>(xh, wq, qkv, B_ * T_, F_, C_);
    }

    // 2) RoPE + split + gain (emits fp16)
    {
        int total = B_ * T_ * H_ * 64;
        rope_kernel<<<total / 256, 256>>>(gain, cosb, sinb);
    }

    // 3) attention (fp16 tensor core)
    {
        size_t smem = (size_t)3 * 128 * QH * sizeof(__half);   // 104448
        cudaFuncSetAttribute(attn_tc, cudaFuncAttributeMaxDynamicSharedMemorySize, (int)smem);
        dim3 grid(T_ / 128, H_, B_);
        attn_tc<<<grid, 256, smem>>>(y);
    }

    // 4) output projection: [4096,2048] x [2048,2048]^T -> out fp32
    {
        dim3 grid(C_ / 128, (B_ * T_) / 128);
        gemm_f16<<<grid, 128, gemm_smem>>>(y, wp, out, B_ * T_, C_, C_);
    }
}

// round 12
// speedup vs baseline: 2.0566x; 1.0425x over previous
#include <cuda_runtime.h>
#include <cuda_fp16.h>
#include <math.h>
#include <float.h>
#include <stdint.h>

#define B_ 2
#define T_ 2048
#define C_ 2048
#define H_ 16
#define D_ 128
#define F_ (3*C_)

// ---------------- scratch ----------------
__device__ float  g_qkv[(size_t)B_ * T_ * F_];      // raw fp32 GEMM output
__device__ __half g_q[(size_t)B_ * H_ * T_ * D_];   // fp16
__device__ __half g_k[(size_t)B_ * H_ * T_ * D_];
__device__ __half g_v[(size_t)B_ * H_ * T_ * D_];
__device__ __half g_y[(size_t)B_ * T_ * C_];
__device__ __half g_xh[(size_t)B_ * T_ * C_];       // fp16 x
__device__ __half g_wq[(size_t)F_ * C_];            // fp16 Wqkv
__device__ __half g_wp[(size_t)C_ * C_];            // fp16 Wproj

// ---------------- helpers ----------------
#define MMA_F16(c, a, b)                                                      \
  asm volatile(                                                               \
      "mma.sync.aligned.m16n8k16.row.col.f32.f16.f16.f32 "                    \
      "{%0,%1,%2,%3}, {%4,%5,%6,%7}, {%8,%9}, {%0,%1,%2,%3};"                 \
      : "+f"((c)[0]), "+f"((c)[1]), "+f"((c)[2]), "+f"((c)[3])                \
      : "r"((a)[0]), "r"((a)[1]), "r"((a)[2]), "r"((a)[3]),                   \
        "r"((b)[0]), "r"((b)[1]))

#define LDSM_X4(r, addr)                                                      \
  asm volatile("ldmatrix.sync.aligned.m8n8.x4.shared.b16 {%0,%1,%2,%3}, [%4];"\
      : "=r"((r)[0]), "=r"((r)[1]), "=r"((r)[2]), "=r"((r)[3])                \
      : "r"(addr))

#define LDSM_X4_T(r, addr)                                                    \
  asm volatile("ldmatrix.sync.aligned.m8n8.x4.trans.shared.b16 {%0,%1,%2,%3}, [%4];"\
      : "=r"((r)[0]), "=r"((r)[1]), "=r"((r)[2]), "=r"((r)[3])                \
      : "r"(addr))

__device__ __forceinline__ uint32_t smem_u32(const void* p) {
    return (uint32_t)__cvta_generic_to_shared(p);
}
__device__ __forceinline__ void cp16(void* sdst, const void* gsrc) {
    uint32_t s = smem_u32(sdst);
    asm volatile("cp.async.cg.shared.global [%0], [%1], 16;" :: "r"(s), "l"(gsrc));
}
#define CP_COMMIT() asm volatile("cp.async.commit_group;" ::)
#define CP_WAIT1()  asm volatile("cp.async.wait_group 1;" ::)
#define CP_WAIT0()  asm volatile("cp.async.wait_group 0;" ::)

__device__ __forceinline__ uint32_t packh2(float x, float y) {
    __half2 h = __floats2half2_rn(x, y);
    return *(uint32_t*)&h;
}

// ---------------- fp32 -> fp16 convert (8 elems/thread) ----------------
__global__ __launch_bounds__(256) void cvt_f16_kernel(const float4* __restrict__ src,
                                                      uint4* __restrict__ dst, int n8)
{
    int i = blockIdx.x * blockDim.x + threadIdx.x;
    if (i < n8) {
        float4 a = src[2 * i];
        float4 b = src[2 * i + 1];
        __half2 h0 = __floats2half2_rn(a.x, a.y);
        __half2 h1 = __floats2half2_rn(a.z, a.w);
        __half2 h2 = __floats2half2_rn(b.x, b.y);
        __half2 h3 = __floats2half2_rn(b.z, b.w);
        uint4 o = {*(uint32_t*)&h0, *(uint32_t*)&h1, *(uint32_t*)&h2, *(uint32_t*)&h3};
        dst[i] = o;
    }
}

// ---------------- fp16 GEMM (unchanged from round 11) -----------------------
#define HSTR 72
#define HS_SZ (128 * HSTR)

__global__ __launch_bounds__(128, 2) void gemm_f16(const __half* __restrict__ A,
                                                   const __half* __restrict__ Bm,
                                                   float* __restrict__ Cm,
                                                   int M, int N, int K)
{
    extern __shared__ __half hsm[];
    __half* As = hsm;
    __half* Bs = hsm + 2 * HS_SZ;

    const int tid  = threadIdx.x;
    const int warp = tid >> 5;
    const int lane = tid & 31;
    const int g    = lane >> 2;
    const int tg   = lane & 3;
    const int lm8  = lane & 7;
    const int lq   = lane >> 3;
    const int wm   = (warp >> 1) * 64;
    const int wn   = (warp & 1) * 64;
    const int m0   = blockIdx.y * 128;
    const int n0   = blockIdx.x * 128;

    const uint32_t sbA = smem_u32(As);
    const uint32_t sbB = smem_u32(Bs);
    const uint32_t aBase = sbA + (uint32_t)((wm + lm8 + ((lq & 1) << 3)) * HSTR) * 2
                               + ((uint32_t)(lq >> 1) << 4);
    const uint32_t bBase = sbB + (uint32_t)((wn + lm8 + ((lq >> 1) << 3)) * HSTR) * 2
                               + ((uint32_t)(lq & 1) << 4);
    const uint32_t stageBytes = HS_SZ * 2;

    float acc[4][8][4];
#pragma unroll
    for (int mi = 0; mi < 4; mi++)
#pragma unroll
        for (int ni = 0; ni < 8; ni++)
#pragma unroll
            for (int c = 0; c < 4; c++) acc[mi][ni][c] = 0.f;

    uint32_t af[2][4][4], bq[2][4][4];

    auto load_stage = [&](int s, int k0) {
#pragma unroll
        for (int t = 0; t < 8; t++) {
            int cid = tid + t * 128;
            int row = cid >> 3;
            int ch8 = (cid & 7) * 8;
            cp16(&As[(size_t)s * HS_SZ + row * HSTR + ch8],
                 A + (size_t)(m0 + row) * K + k0 + ch8);
            cp16(&Bs[(size_t)s * HS_SZ + row * HSTR + ch8],
                 Bm + (size_t)(n0 + row) * K + k0 + ch8);
        }
    };

#define LD_FRAG(buf, sOff, ks)                                                  \
    do {                                                                        \
        _Pragma("unroll")                                                       \
        for (int mi = 0; mi < 4; mi++)                                          \
            LDSM_X4(af[buf][mi], aBase + (sOff) + (uint32_t)(mi * 16 * HSTR * 2) + (ks) * 32); \
        _Pragma("unroll")                                                       \
        for (int p = 0; p < 4; p++)                                             \
            LDSM_X4(bq[buf][p], bBase + (sOff) + (uint32_t)(p * 16 * HSTR * 2) + (ks) * 32);   \
    } while (0)

#define DO_MMA(buf)                                                             \
    do {                                                                        \
        _Pragma("unroll")                                                       \
        for (int mi = 0; mi < 4; mi++)                                          \
            _Pragma("unroll")                                                   \
            for (int p = 0; p < 4; p++) {                                       \
                MMA_F16(acc[mi][2 * p],     af[buf][mi], bq[buf][p]);           \
                MMA_F16(acc[mi][2 * p + 1], af[buf][mi], bq[buf][p] + 2);       \
            }                                                                   \
    } while (0)

    load_stage(0, 0);  CP_COMMIT();
    load_stage(1, 64); CP_COMMIT();
    CP_WAIT1();
    __syncthreads();

    const int nK = K / 64;
    int cur = 0;
    LD_FRAG(0, 0u, 0);

    for (int kt = 0; kt < nK; kt++) {
        const uint32_t sOff = (uint32_t)cur * stageBytes;
#pragma unroll
        for (int ks = 0; ks < 4; ks++) {
            const int cb = ks & 1;
            if (ks < 3) {
                if (cb) LD_FRAG(0, sOff, ks + 1);
                else    LD_FRAG(1, sOff, ks + 1);
            }
            if (cb) DO_MMA(1); else DO_MMA(0);
        }
        __syncthreads();
        if (kt + 2 < nK) load_stage(cur, (kt + 2) * 64);
        CP_COMMIT();
        CP_WAIT1();
        __syncthreads();
        cur ^= 1;
        if (kt + 1 < nK)
            LD_FRAG(0, (uint32_t)cur * stageBytes, 0);
    }

#pragma unroll
    for (int mi = 0; mi < 4; mi++) {
#pragma unroll
        for (int ni = 0; ni < 8; ni++) {
            const int r = m0 + wm + mi * 16 + g;
            const int c = n0 + wn + ni * 8 + 2 * tg;
            float2 v0 = {acc[mi][ni][0], acc[mi][ni][1]};
            float2 v1 = {acc[mi][ni][2], acc[mi][ni][3]};
            *(float2*)&Cm[(size_t)r * N + c]       = v0;
            *(float2*)&Cm[(size_t)(r + 8) * N + c] = v1;
        }
    }
#undef LD_FRAG
#undef DO_MMA
}

// ---------------- RoPE + split + gain-fold (emits fp16 q/k/v) ----------------
__global__ __launch_bounds__(256) void rope_kernel(const float* __restrict__ gain,
                                                   const float* __restrict__ cosb,
                                                   const float* __restrict__ sinb)
{
    int idx = blockIdx.x * blockDim.x + threadIdx.x;
    int d = idx & 63;
    int h = (idx >> 6) & 15;
    int t = (idx >> 10) & 2047;
    int b = idx >> 21;

    size_t base = ((size_t)(b * T_ + t)) * F_ + h * D_;
    float c = cosb[t * 64 + d];
    float s = sinb[t * 64 + d];

    float q1 = g_qkv[base + d],            q2 = g_qkv[base + d + 64];
    float k1 = g_qkv[base + C_ + d],       k2 = g_qkv[base + C_ + d + 64];
    float v1 = g_qkv[base + 2 * C_ + d],   v2 = g_qkv[base + 2 * C_ + d + 64];

    float gn = gain[h] * rsqrtf((float)D_);
    size_t ob = ((size_t)((b * H_ + h) * T_ + t)) * D_;

    g_q[ob + d]      = __float2half_rn((q1 * c - q2 * s) * gn);
    g_q[ob + d + 64] = __float2half_rn((q2 * c + q1 * s) * gn);
    g_k[ob + d]      = __float2half_rn(k1 * c - k2 * s);
    g_k[ob + d + 64] = __float2half_rn(k2 * c + k1 * s);
    g_v[ob + d]      = __float2half_rn(v1);
    g_v[ob + d + 64] = __float2half_rn(v2);
}

// ---------------- fp16 flash attention: no P smem, K/V cp.async overlap ------
#define QH 136    // halves per row (272B stride, conflict-free)

__global__ __launch_bounds__(256, 1) void attn_tc(__half* __restrict__ Y)
{
    extern __shared__ __half ham[];
    __half* sQ = ham;                        // [128][QH]
    __half* sK = ham + 128 * QH;             // [128][QH]
    __half* sV = ham + 256 * QH;             // [128][QH]

    const int tid  = threadIdx.x;
    const int warp = tid >> 5;
    const int lane = tid & 31;
    const int g    = lane >> 2;
    const int tg   = lane & 3;
    const int lm8  = lane & 7;
    const int lq   = lane >> 3;
    const int qb = blockIdx.x;
    const int h  = blockIdx.y;
    const int b  = blockIdx.z;
    const int q0 = qb * 128;
    const size_t bh = ((size_t)(b * H_ + h)) * T_ * D_;

    const uint32_t qAddr = smem_u32(sQ)
        + (uint32_t)((16 * warp + lm8 + ((lq & 1) << 3)) * QH) * 2
        + ((uint32_t)(lq >> 1) << 4);
    const uint32_t kAddr = smem_u32(sK)
        + (uint32_t)((lm8 + ((lq >> 1) << 3)) * QH) * 2
        + ((uint32_t)(lq & 1) << 4);
    const uint32_t vAddr = smem_u32(sV)
        + (uint32_t)((lm8 + ((lq & 1) << 3)) * QH) * 2
        + ((uint32_t)(lq >> 1) << 4);

    // async loaders: 128 rows x 16 16B-chunks = 2048 -> 8/thread
    auto load_k = [&](int k0) {
#pragma unroll
        for (int i = 0; i < 8; i++) {
            int e = tid + i * 256;
            int row = e >> 4;
            int col = (e & 15) * 8;
            cp16(&sK[row * QH + col], g_k + bh + (size_t)(k0 + row) * D_ + col);
        }
    };
    auto load_v = [&](int k0) {
#pragma unroll
        for (int i = 0; i < 8; i++) {
            int e = tid + i * 256;
            int row = e >> 4;
            int col = (e & 15) * 8;
            cp16(&sV[row * QH + col], g_v + bh + (size_t)(k0 + row) * D_ + col);
        }
    };

    // K_0 in flight, then load Q tile (plain stores)
    load_k(0); CP_COMMIT();
    for (int i = 0; i < 8; i++) {
        int e = tid + i * 256;
        int row = e >> 4;
        int col = (e & 15) * 8;
        *(uint4*)&sQ[row * QH + col] = *(const uint4*)(g_q + bh + (size_t)(q0 + row) * D_ + col);
    }

    float yacc[16][4];
#pragma unroll
    for (int nt = 0; nt < 16; nt++)
#pragma unroll
        for (int c = 0; c < 4; c++) yacc[nt][c] = 0.f;
    float m0 = -1e30f, m1 = -1e30f, l0 = 0.f, l1 = 0.f;

    for (int kt = 0; kt <= qb; kt++) {
        const int k0 = kt * 128;

        CP_WAIT0();
        __syncthreads();                 // K_kt (and Q on first iter) visible

        load_v(k0); CP_COMMIT();         // V_kt overlaps S + softmax

        // S = Q K^T  (D=128 -> 8 k16 steps)
        float sacc[16][4];
#pragma unroll
        for (int nt = 0; nt < 16; nt++)
#pragma unroll
            for (int c = 0; c < 4; c++) sacc[nt][c] = 0.f;

#pragma unroll
        for (int ks = 0; ks < 8; ks++) {
            uint32_t a[4];
            LDSM_X4(a, qAddr + ks * 32);
#pragma unroll
            for (int p = 0; p < 8; p++) {
                uint32_t bqv[4];
                LDSM_X4(bqv, kAddr + (uint32_t)(p * 16 * QH * 2) + ks * 32);
                MMA_F16(sacc[2 * p],     a, bqv);
                MMA_F16(sacc[2 * p + 1], a, bqv + 2);
            }
        }

        // causal mask on diagonal tile
        if (kt == qb) {
            const int r0g = q0 + 16 * warp + g;
            const int r1g = r0g + 8;
#pragma unroll
            for (int nt = 0; nt < 16; nt++) {
                int c0 = k0 + nt * 8 + 2 * tg;
                if (c0     > r0g) sacc[nt][0] = -1e30f;
                if (c0 + 1 > r0g) sacc[nt][1] = -1e30f;
                if (c0     > r1g) sacc[nt][2] = -1e30f;
                if (c0 + 1 > r1g) sacc[nt][3] = -1e30f;
            }
        }

        // online softmax (registers only — overlaps V cp.async)
        float mx0 = -1e30f, mx1 = -1e30f;
#pragma unroll
        for (int nt = 0; nt < 16; nt++) {
            mx0 = fmaxf(mx0, fmaxf(sacc[nt][0], sacc[nt][1]));
            mx1 = fmaxf(mx1, fmaxf(sacc[nt][2], sacc[nt][3]));
        }
        mx0 = fmaxf(mx0, __shfl_xor_sync(0xffffffffu, mx0, 1));
        mx0 = fmaxf(mx0, __shfl_xor_sync(0xffffffffu, mx0, 2));
        mx1 = fmaxf(mx1, __shfl_xor_sync(0xffffffffu, mx1, 1));
        mx1 = fmaxf(mx1, __shfl_xor_sync(0xffffffffu, mx1, 2));

        float nm0 = fmaxf(m0, mx0), nm1 = fmaxf(m1, mx1);
        float cf0 = __expf(m0 - nm0), cf1 = __expf(m1 - nm1);
        m0 = nm0; m1 = nm1;

        float rs0 = 0.f, rs1 = 0.f;
#pragma unroll
        for (int nt = 0; nt < 16; nt++) {
            sacc[nt][0] = __expf(sacc[nt][0] - nm0);
            sacc[nt][1] = __expf(sacc[nt][1] - nm0);
            sacc[nt][2] = __expf(sacc[nt][2] - nm1);
            sacc[nt][3] = __expf(sacc[nt][3] - nm1);
            rs0 += sacc[nt][0] + sacc[nt][1];
            rs1 += sacc[nt][2] + sacc[nt][3];
        }
        rs0 += __shfl_xor_sync(0xffffffffu, rs0, 1);
        rs0 += __shfl_xor_sync(0xffffffffu, rs0, 2);
        rs1 += __shfl_xor_sync(0xffffffffu, rs1, 1);
        rs1 += __shfl_xor_sync(0xffffffffu, rs1, 2);
        l0 = l0 * cf0 + rs0;
        l1 = l1 * cf1 + rs1;

#pragma unroll
        for (int nt = 0; nt < 16; nt++) {
            yacc[nt][0] *= cf0; yacc[nt][1] *= cf0;
            yacc[nt][2] *= cf1; yacc[nt][3] *= cf1;
        }

        // P fragments: direct register repack (bitwise == old smem round-trip)
        uint32_t pf[8][4];
#pragma unroll
        for (int ks = 0; ks < 8; ks++) {
            pf[ks][0] = packh2(sacc[2 * ks][0],     sacc[2 * ks][1]);
            pf[ks][1] = packh2(sacc[2 * ks][2],     sacc[2 * ks][3]);
            pf[ks][2] = packh2(sacc[2 * ks + 1][0], sacc[2 * ks + 1][1]);
            pf[ks][3] = packh2(sacc[2 * ks + 1][2], sacc[2 * ks + 1][3]);
        }

        CP_WAIT0();
        __syncthreads();                 // V_kt visible; all warps done with K

        if (kt < qb) { load_k(k0 + 128); CP_COMMIT(); }   // K_{kt+1} overlaps PV

        // yacc += P V  (V^T via ldmatrix.trans)
#pragma unroll
        for (int ks = 0; ks < 8; ks++) {
#pragma unroll
            for (int p = 0; p < 8; p++) {
                uint32_t bqv[4];
                LDSM_X4_T(bqv, vAddr + (uint32_t)(ks * 16 * QH * 2) + p * 32);
                MMA_F16(yacc[2 * p],     pf[ks], bqv);
                MMA_F16(yacc[2 * p + 1], pf[ks], bqv + 2);
            }
        }
        // no barrier needed: next iter's V writes come only after its first
        // __syncthreads, which every warp reaches after finishing this PV loop
    }

    // epilogue: fp16 y (feeds proj GEMM)
    const float inv0 = 1.f / l0;
    const float inv1 = 1.f / l1;
    const int r0g = q0 + 16 * warp + g;
    const int r1g = r0g + 8;
#pragma unroll
    for (int nt = 0; nt < 16; nt++) {
        int col = h * D_ + nt * 8 + 2 * tg;
        *(__half2*)&Y[(size_t)(b * T_ + r0g) * C_ + col] =
            __floats2half2_rn(yacc[nt][0] * inv0, yacc[nt][1] * inv0);
        *(__half2*)&Y[(size_t)(b * T_ + r1g) * C_ + col] =
            __floats2half2_rn(yacc[nt][2] * inv1, yacc[nt][3] * inv1);
    }
}

// ---------------- launch ----------------
extern "C" void kernel_launch(void* const* d_in, const int* in_sizes, int n_in,
                              void* d_out, int out_size)
{
    const float* x     = (const float*)d_in[0];
    const float* Wqkv  = (const float*)d_in[1];
    const float* Wproj = (const float*)d_in[2];
    const float* gain  = (const float*)d_in[3];
    const float* cosb  = (const float*)d_in[4];
    const float* sinb  = (const float*)d_in[5];
    float* out = (float*)d_out;

    float* qkv;
    __half *y, *xh, *wq, *wp;
    cudaGetSymbolAddress((void**)&qkv, g_qkv);
    cudaGetSymbolAddress((void**)&y,   g_y);
    cudaGetSymbolAddress((void**)&xh,  g_xh);
    cudaGetSymbolAddress((void**)&wq,  g_wq);
    cudaGetSymbolAddress((void**)&wp,  g_wp);

    const size_t gemm_smem = (size_t)4 * HS_SZ * sizeof(__half);   // 73728
    cudaFuncSetAttribute(gemm_f16, cudaFuncAttributeMaxDynamicSharedMemorySize, (int)gemm_smem);

    // 0) convert inputs to fp16
    {
        int n8x = (B_ * T_ * C_) / 8;
        cvt_f16_kernel<<<(n8x + 255) / 256, 256>>>((const float4*)x, (uint4*)xh, n8x);
        int n8q = (F_ * C_) / 8;
        cvt_f16_kernel<<<(n8q + 255) / 256, 256>>>((const float4*)Wqkv, (uint4*)wq, n8q);
        int n8p = (C_ * C_) / 8;
        cvt_f16_kernel<<<(n8p + 255) / 256, 256>>>((const float4*)Wproj, (uint4*)wp, n8p);
    }

    // 1) QKV GEMM: [4096,2048] x [6144,2048]^T -> [4096,6144] fp32
    {
        dim3 grid(F_ / 128, (B_ * T_) / 128);
        gemm_f16<<<grid, 128, gemm_smem>>>(xh, wq, qkv, B_ * T_, F_, C_);
    }

    // 2) RoPE + split + gain (emits fp16)
    {
        int total = B_ * T_ * H_ * 64;
        rope_kernel<<<total / 256, 256>>>(gain, cosb, sinb);
    }

    // 3) attention (fp16 tensor core, no P smem, K/V overlap)
    {
        size_t smem = (size_t)3 * 128 * QH * sizeof(__half);   // 104448
        cudaFuncSetAttribute(attn_tc, cudaFuncAttributeMaxDynamicSharedMemorySize, (int)smem);
        dim3 grid(T_ / 128, H_, B_);
        attn_tc<<<grid, 256, smem>>>(y);
    }

    // 4) output projection: [4096,2048] x [2048,2048]^T -> out fp32
    {
        dim3 grid(C_ / 128, (B_ * T_) / 128);
        gemm_f16<<<grid, 128, gemm_smem>>>(y, wp, out, B_ * T_, C_, C_);
    }
}

// round 13
// speedup vs baseline: 2.0843x; 1.0134x over previous
#include <cuda_runtime.h>
#include <cuda_fp16.h>
#include <math.h>
#include <float.h>
#include <stdint.h>

#define B_ 2
#define T_ 2048
#define C_ 2048
#define H_ 16
#define D_ 128
#define F_ (3*C_)

// ---------------- scratch ----------------
__device__ float  g_qkv[(size_t)B_ * T_ * F_];      // raw fp32 GEMM output
__device__ __half g_q[(size_t)B_ * H_ * T_ * D_];   // fp16
__device__ __half g_k[(size_t)B_ * H_ * T_ * D_];
__device__ __half g_v[(size_t)B_ * H_ * T_ * D_];
__device__ __half g_y[(size_t)B_ * T_ * C_];
__device__ __half g_xh[(size_t)B_ * T_ * C_];       // fp16 x
__device__ __half g_wq[(size_t)F_ * C_];            // fp16 Wqkv
__device__ __half g_wp[(size_t)C_ * C_];            // fp16 Wproj

// ---------------- helpers ----------------
#define MMA_F16(c, a, b)                                                      \
  asm volatile(                                                               \
      "mma.sync.aligned.m16n8k16.row.col.f32.f16.f16.f32 "                    \
      "{%0,%1,%2,%3}, {%4,%5,%6,%7}, {%8,%9}, {%0,%1,%2,%3};"                 \
      : "+f"((c)[0]), "+f"((c)[1]), "+f"((c)[2]), "+f"((c)[3])                \
      : "r"((a)[0]), "r"((a)[1]), "r"((a)[2]), "r"((a)[3]),                   \
        "r"((b)[0]), "r"((b)[1]))

#define LDSM_X4(r, addr)                                                      \
  asm volatile("ldmatrix.sync.aligned.m8n8.x4.shared.b16 {%0,%1,%2,%3}, [%4];"\
      : "=r"((r)[0]), "=r"((r)[1]), "=r"((r)[2]), "=r"((r)[3])                \
      : "r"(addr))

#define LDSM_X4_T(r, addr)                                                    \
  asm volatile("ldmatrix.sync.aligned.m8n8.x4.trans.shared.b16 {%0,%1,%2,%3}, [%4];"\
      : "=r"((r)[0]), "=r"((r)[1]), "=r"((r)[2]), "=r"((r)[3])                \
      : "r"(addr))

__device__ __forceinline__ uint32_t smem_u32(const void* p) {
    return (uint32_t)__cvta_generic_to_shared(p);
}
__device__ __forceinline__ void cp16(void* sdst, const void* gsrc) {
    uint32_t s = smem_u32(sdst);
    asm volatile("cp.async.cg.shared.global [%0], [%1], 16;" :: "r"(s), "l"(gsrc));
}
#define CP_COMMIT() asm volatile("cp.async.commit_group;" ::)
#define CP_WAIT1()  asm volatile("cp.async.wait_group 1;" ::)
#define CP_WAIT0()  asm volatile("cp.async.wait_group 0;" ::)

__device__ __forceinline__ uint32_t packh2(float x, float y) {
    __half2 h = __floats2half2_rn(x, y);
    return *(uint32_t*)&h;
}

// ---------------- fp32 -> fp16 convert (8 elems/thread) ----------------
__global__ __launch_bounds__(256) void cvt_f16_kernel(const float4* __restrict__ src,
                                                      uint4* __restrict__ dst, int n8)
{
    int i = blockIdx.x * blockDim.x + threadIdx.x;
    if (i < n8) {
        float4 a = src[2 * i];
        float4 b = src[2 * i + 1];
        __half2 h0 = __floats2half2_rn(a.x, a.y);
        __half2 h1 = __floats2half2_rn(a.z, a.w);
        __half2 h2 = __floats2half2_rn(b.x, b.y);
        __half2 h3 = __floats2half2_rn(b.z, b.w);
        uint4 o = {*(uint32_t*)&h0, *(uint32_t*)&h1, *(uint32_t*)&h2, *(uint32_t*)&h3};
        dst[i] = o;
    }
}

// ---------------- fp16 GEMM (unchanged) --------------------------------------
#define HSTR 72
#define HS_SZ (128 * HSTR)

__global__ __launch_bounds__(128, 2) void gemm_f16(const __half* __restrict__ A,
                                                   const __half* __restrict__ Bm,
                                                   float* __restrict__ Cm,
                                                   int M, int N, int K)
{
    extern __shared__ __half hsm[];
    __half* As = hsm;
    __half* Bs = hsm + 2 * HS_SZ;

    const int tid  = threadIdx.x;
    const int warp = tid >> 5;
    const int lane = tid & 31;
    const int g    = lane >> 2;
    const int tg   = lane & 3;
    const int lm8  = lane & 7;
    const int lq   = lane >> 3;
    const int wm   = (warp >> 1) * 64;
    const int wn   = (warp & 1) * 64;
    const int m0   = blockIdx.y * 128;
    const int n0   = blockIdx.x * 128;

    const uint32_t sbA = smem_u32(As);
    const uint32_t sbB = smem_u32(Bs);
    const uint32_t aBase = sbA + (uint32_t)((wm + lm8 + ((lq & 1) << 3)) * HSTR) * 2
                               + ((uint32_t)(lq >> 1) << 4);
    const uint32_t bBase = sbB + (uint32_t)((wn + lm8 + ((lq >> 1) << 3)) * HSTR) * 2
                               + ((uint32_t)(lq & 1) << 4);
    const uint32_t stageBytes = HS_SZ * 2;

    float acc[4][8][4];
#pragma unroll
    for (int mi = 0; mi < 4; mi++)
#pragma unroll
        for (int ni = 0; ni < 8; ni++)
#pragma unroll
            for (int c = 0; c < 4; c++) acc[mi][ni][c] = 0.f;

    uint32_t af[2][4][4], bq[2][4][4];

    auto load_stage = [&](int s, int k0) {
#pragma unroll
        for (int t = 0; t < 8; t++) {
            int cid = tid + t * 128;
            int row = cid >> 3;
            int ch8 = (cid & 7) * 8;
            cp16(&As[(size_t)s * HS_SZ + row * HSTR + ch8],
                 A + (size_t)(m0 + row) * K + k0 + ch8);
            cp16(&Bs[(size_t)s * HS_SZ + row * HSTR + ch8],
                 Bm + (size_t)(n0 + row) * K + k0 + ch8);
        }
    };

#define LD_FRAG(buf, sOff, ks)                                                  \
    do {                                                                        \
        _Pragma("unroll")                                                       \
        for (int mi = 0; mi < 4; mi++)                                          \
            LDSM_X4(af[buf][mi], aBase + (sOff) + (uint32_t)(mi * 16 * HSTR * 2) + (ks) * 32); \
        _Pragma("unroll")                                                       \
        for (int p = 0; p < 4; p++)                                             \
            LDSM_X4(bq[buf][p], bBase + (sOff) + (uint32_t)(p * 16 * HSTR * 2) + (ks) * 32);   \
    } while (0)

#define DO_MMA(buf)                                                             \
    do {                                                                        \
        _Pragma("unroll")                                                       \
        for (int mi = 0; mi < 4; mi++)                                          \
            _Pragma("unroll")                                                   \
            for (int p = 0; p < 4; p++) {                                       \
                MMA_F16(acc[mi][2 * p],     af[buf][mi], bq[buf][p]);           \
                MMA_F16(acc[mi][2 * p + 1], af[buf][mi], bq[buf][p] + 2);       \
            }                                                                   \
    } while (0)

    load_stage(0, 0);  CP_COMMIT();
    load_stage(1, 64); CP_COMMIT();
    CP_WAIT1();
    __syncthreads();

    const int nK = K / 64;
    int cur = 0;
    LD_FRAG(0, 0u, 0);

    for (int kt = 0; kt < nK; kt++) {
        const uint32_t sOff = (uint32_t)cur * stageBytes;
#pragma unroll
        for (int ks = 0; ks < 4; ks++) {
            const int cb = ks & 1;
            if (ks < 3) {
                if (cb) LD_FRAG(0, sOff, ks + 1);
                else    LD_FRAG(1, sOff, ks + 1);
            }
            if (cb) DO_MMA(1); else DO_MMA(0);
        }
        __syncthreads();
        if (kt + 2 < nK) load_stage(cur, (kt + 2) * 64);
        CP_COMMIT();
        CP_WAIT1();
        __syncthreads();
        cur ^= 1;
        if (kt + 1 < nK)
            LD_FRAG(0, (uint32_t)cur * stageBytes, 0);
    }

#pragma unroll
    for (int mi = 0; mi < 4; mi++) {
#pragma unroll
        for (int ni = 0; ni < 8; ni++) {
            const int r = m0 + wm + mi * 16 + g;
            const int c = n0 + wn + ni * 8 + 2 * tg;
            float2 v0 = {acc[mi][ni][0], acc[mi][ni][1]};
            float2 v1 = {acc[mi][ni][2], acc[mi][ni][3]};
            *(float2*)&Cm[(size_t)r * N + c]       = v0;
            *(float2*)&Cm[(size_t)(r + 8) * N + c] = v1;
        }
    }
#undef LD_FRAG
#undef DO_MMA
}

// ---------------- RoPE + split + gain-fold (emits fp16 q/k/v) ----------------
__global__ __launch_bounds__(256) void rope_kernel(const float* __restrict__ gain,
                                                   const float* __restrict__ cosb,
                                                   const float* __restrict__ sinb)
{
    int idx = blockIdx.x * blockDim.x + threadIdx.x;
    int d = idx & 63;
    int h = (idx >> 6) & 15;
    int t = (idx >> 10) & 2047;
    int b = idx >> 21;

    size_t base = ((size_t)(b * T_ + t)) * F_ + h * D_;
    float c = cosb[t * 64 + d];
    float s = sinb[t * 64 + d];

    float q1 = g_qkv[base + d],            q2 = g_qkv[base + d + 64];
    float k1 = g_qkv[base + C_ + d],       k2 = g_qkv[base + C_ + d + 64];
    float v1 = g_qkv[base + 2 * C_ + d],   v2 = g_qkv[base + 2 * C_ + d + 64];

    float gn = gain[h] * rsqrtf((float)D_);
    size_t ob = ((size_t)((b * H_ + h) * T_ + t)) * D_;

    g_q[ob + d]      = __float2half_rn((q1 * c - q2 * s) * gn);
    g_q[ob + d + 64] = __float2half_rn((q2 * c + q1 * s) * gn);
    g_k[ob + d]      = __float2half_rn(k1 * c - k2 * s);
    g_k[ob + d + 64] = __float2half_rn(k2 * c + k1 * s);
    g_v[ob + d]      = __float2half_rn(v1);
    g_v[ob + d + 64] = __float2half_rn(v2);
}

// ---------------- fp16 flash attention: LPT order + hoisted Q fragments ------
#define QH 136    // halves per row (272B stride, conflict-free)

__global__ __launch_bounds__(256, 1) void attn_tc(__half* __restrict__ Y)
{
    extern __shared__ __half ham[];
    __half* sQ = ham;                        // [128][QH]
    __half* sK = ham + 128 * QH;             // [128][QH]
    __half* sV = ham + 256 * QH;             // [128][QH]

    const int tid  = threadIdx.x;
    const int warp = tid >> 5;
    const int lane = tid & 31;
    const int g    = lane >> 2;
    const int tg   = lane & 3;
    const int lm8  = lane & 7;
    const int lq   = lane >> 3;
    // LPT: heaviest q-blocks (largest qb) launch first
    const int qb = (T_ / 128 - 1) - blockIdx.x;
    const int h  = blockIdx.y;
    const int b  = blockIdx.z;
    const int q0 = qb * 128;
    const size_t bh = ((size_t)(b * H_ + h)) * T_ * D_;

    const uint32_t qAddr = smem_u32(sQ)
        + (uint32_t)((16 * warp + lm8 + ((lq & 1) << 3)) * QH) * 2
        + ((uint32_t)(lq >> 1) << 4);
    const uint32_t kAddr = smem_u32(sK)
        + (uint32_t)((lm8 + ((lq >> 1) << 3)) * QH) * 2
        + ((uint32_t)(lq & 1) << 4);
    const uint32_t vAddr = smem_u32(sV)
        + (uint32_t)((lm8 + ((lq & 1) << 3)) * QH) * 2
        + ((uint32_t)(lq >> 1) << 4);

    auto load_k = [&](int k0) {
#pragma unroll
        for (int i = 0; i < 8; i++) {
            int e = tid + i * 256;
            int row = e >> 4;
            int col = (e & 15) * 8;
            cp16(&sK[row * QH + col], g_k + bh + (size_t)(k0 + row) * D_ + col);
        }
    };
    auto load_v = [&](int k0) {
#pragma unroll
        for (int i = 0; i < 8; i++) {
            int e = tid + i * 256;
            int row = e >> 4;
            int col = (e & 15) * 8;
            cp16(&sV[row * QH + col], g_v + bh + (size_t)(k0 + row) * D_ + col);
        }
    };

    // prologue: K_0 in flight; Q tile via plain stores
    load_k(0); CP_COMMIT();
    for (int i = 0; i < 8; i++) {
        int e = tid + i * 256;
        int row = e >> 4;
        int col = (e & 15) * 8;
        *(uint4*)&sQ[row * QH + col] = *(const uint4*)(g_q + bh + (size_t)(q0 + row) * D_ + col);
    }
    __syncthreads();                     // Q visible to all warps

    // hoist Q fragments (loop-invariant): 8 k16-steps x 4 regs
    uint32_t qf[8][4];
#pragma unroll
    for (int ks = 0; ks < 8; ks++)
        LDSM_X4(qf[ks], qAddr + ks * 32);

    float yacc[16][4];
#pragma unroll
    for (int nt = 0; nt < 16; nt++)
#pragma unroll
        for (int c = 0; c < 4; c++) yacc[nt][c] = 0.f;
    float m0 = -1e30f, m1 = -1e30f, l0 = 0.f, l1 = 0.f;

    for (int kt = 0; kt <= qb; kt++) {
        const int k0 = kt * 128;

        CP_WAIT0();
        __syncthreads();                 // K_kt visible; prior PV done (sV free)

        load_v(k0); CP_COMMIT();         // V_kt overlaps S + softmax

        // S = Q K^T
        float sacc[16][4];
#pragma unroll
        for (int nt = 0; nt < 16; nt++)
#pragma unroll
            for (int c = 0; c < 4; c++) sacc[nt][c] = 0.f;

#pragma unroll
        for (int ks = 0; ks < 8; ks++) {
#pragma unroll
            for (int p = 0; p < 8; p++) {
                uint32_t bqv[4];
                LDSM_X4(bqv, kAddr + (uint32_t)(p * 16 * QH * 2) + ks * 32);
                MMA_F16(sacc[2 * p],     qf[ks], bqv);
                MMA_F16(sacc[2 * p + 1], qf[ks], bqv + 2);
            }
        }

        // causal mask on diagonal tile
        if (kt == qb) {
            const int r0g = q0 + 16 * warp + g;
            const int r1g = r0g + 8;
#pragma unroll
            for (int nt = 0; nt < 16; nt++) {
                int c0 = k0 + nt * 8 + 2 * tg;
                if (c0     > r0g) sacc[nt][0] = -1e30f;
                if (c0 + 1 > r0g) sacc[nt][1] = -1e30f;
                if (c0     > r1g) sacc[nt][2] = -1e30f;
                if (c0 + 1 > r1g) sacc[nt][3] = -1e30f;
            }
        }

        // online softmax (registers only — overlaps V cp.async)
        float mx0 = -1e30f, mx1 = -1e30f;
#pragma unroll
        for (int nt = 0; nt < 16; nt++) {
            mx0 = fmaxf(mx0, fmaxf(sacc[nt][0], sacc[nt][1]));
            mx1 = fmaxf(mx1, fmaxf(sacc[nt][2], sacc[nt][3]));
        }
        mx0 = fmaxf(mx0, __shfl_xor_sync(0xffffffffu, mx0, 1));
        mx0 = fmaxf(mx0, __shfl_xor_sync(0xffffffffu, mx0, 2));
        mx1 = fmaxf(mx1, __shfl_xor_sync(0xffffffffu, mx1, 1));
        mx1 = fmaxf(mx1, __shfl_xor_sync(0xffffffffu, mx1, 2));

        float nm0 = fmaxf(m0, mx0), nm1 = fmaxf(m1, mx1);
        float cf0 = __expf(m0 - nm0), cf1 = __expf(m1 - nm1);
        m0 = nm0; m1 = nm1;

        float rs0 = 0.f, rs1 = 0.f;
#pragma unroll
        for (int nt = 0; nt < 16; nt++) {
            sacc[nt][0] = __expf(sacc[nt][0] - nm0);
            sacc[nt][1] = __expf(sacc[nt][1] - nm0);
            sacc[nt][2] = __expf(sacc[nt][2] - nm1);
            sacc[nt][3] = __expf(sacc[nt][3] - nm1);
            rs0 += sacc[nt][0] + sacc[nt][1];
            rs1 += sacc[nt][2] + sacc[nt][3];
        }
        rs0 += __shfl_xor_sync(0xffffffffu, rs0, 1);
        rs0 += __shfl_xor_sync(0xffffffffu, rs0, 2);
        rs1 += __shfl_xor_sync(0xffffffffu, rs1, 1);
        rs1 += __shfl_xor_sync(0xffffffffu, rs1, 2);
        l0 = l0 * cf0 + rs0;
        l1 = l1 * cf1 + rs1;

#pragma unroll
        for (int nt = 0; nt < 16; nt++) {
            yacc[nt][0] *= cf0; yacc[nt][1] *= cf0;
            yacc[nt][2] *= cf1; yacc[nt][3] *= cf1;
        }

        // P fragments: direct register repack
        uint32_t pf[8][4];
#pragma unroll
        for (int ks = 0; ks < 8; ks++) {
            pf[ks][0] = packh2(sacc[2 * ks][0],     sacc[2 * ks][1]);
            pf[ks][1] = packh2(sacc[2 * ks][2],     sacc[2 * ks][3]);
            pf[ks][2] = packh2(sacc[2 * ks + 1][0], sacc[2 * ks + 1][1]);
            pf[ks][3] = packh2(sacc[2 * ks + 1][2], sacc[2 * ks + 1][3]);
        }

        CP_WAIT0();
        __syncthreads();                 // V_kt visible; all warps done with K

        if (kt < qb) { load_k(k0 + 128); CP_COMMIT(); }   // K_{kt+1} overlaps PV

        // yacc += P V  (V^T via ldmatrix.trans)
#pragma unroll
        for (int ks = 0; ks < 8; ks++) {
#pragma unroll
            for (int p = 0; p < 8; p++) {
                uint32_t bqv[4];
                LDSM_X4_T(bqv, vAddr + (uint32_t)(ks * 16 * QH * 2) + p * 32);
                MMA_F16(yacc[2 * p],     pf[ks], bqv);
                MMA_F16(yacc[2 * p + 1], pf[ks], bqv + 2);
            }
        }
    }

    // epilogue: fp16 y (feeds proj GEMM)
    const float inv0 = 1.f / l0;
    const float inv1 = 1.f / l1;
    const int r0g = q0 + 16 * warp + g;
    const int r1g = r0g + 8;
#pragma unroll
    for (int nt = 0; nt < 16; nt++) {
        int col = h * D_ + nt * 8 + 2 * tg;
        *(__half2*)&Y[(size_t)(b * T_ + r0g) * C_ + col] =
            __floats2half2_rn(yacc[nt][0] * inv0, yacc[nt][1] * inv0);
        *(__half2*)&Y[(size_t)(b * T_ + r1g) * C_ + col] =
            __floats2half2_rn(yacc[nt][2] * inv1, yacc[nt][3] * inv1);
    }
}

// ---------------- launch ----------------
extern "C" void kernel_launch(void* const* d_in, const int* in_sizes, int n_in,
                              void* d_out, int out_size)
{
    const float* x     = (const float*)d_in[0];
    const float* Wqkv  = (const float*)d_in[1];
    const float* Wproj = (const float*)d_in[2];
    const float* gain  = (const float*)d_in[3];
    const float* cosb  = (const float*)d_in[4];
    const float* sinb  = (const float*)d_in[5];
    float* out = (float*)d_out;

    float* qkv;
    __half *y, *xh, *wq, *wp;
    cudaGetSymbolAddress((void**)&qkv, g_qkv);
    cudaGetSymbolAddress((void**)&y,   g_y);
    cudaGetSymbolAddress((void**)&xh,  g_xh);
    cudaGetSymbolAddress((void**)&wq,  g_wq);
    cudaGetSymbolAddress((void**)&wp,  g_wp);

    const size_t gemm_smem = (size_t)4 * HS_SZ * sizeof(__half);   // 73728
    cudaFuncSetAttribute(gemm_f16, cudaFuncAttributeMaxDynamicSharedMemorySize, (int)gemm_smem);

    // 0) convert inputs to fp16
    {
        int n8x = (B_ * T_ * C_) / 8;
        cvt_f16_kernel<<<(n8x + 255) / 256, 256>>>((const float4*)x, (uint4*)xh, n8x);
        int n8q = (F_ * C_) / 8;
        cvt_f16_kernel<<<(n8q + 255) / 256, 256>>>((const float4*)Wqkv, (uint4*)wq, n8q);
        int n8p = (C_ * C_) / 8;
        cvt_f16_kernel<<<(n8p + 255) / 256, 256>>>((const float4*)Wproj, (uint4*)wp, n8p);
    }

    // 1) QKV GEMM: [4096,2048] x [6144,2048]^T -> [4096,6144] fp32
    {
        dim3 grid(F_ / 128, (B_ * T_) / 128);
        gemm_f16<<<grid, 128, gemm_smem>>>(xh, wq, qkv, B_ * T_, F_, C_);
    }

    // 2) RoPE + split + gain (emits fp16)
    {
        int total = B_ * T_ * H_ * 64;
        rope_kernel<<<total / 256, 256>>>(gain, cosb, sinb);
    }

    // 3) attention (fp16 tensor core, LPT order, hoisted Q frags)
    {
        size_t smem = (size_t)3 * 128 * QH * sizeof(__half);   // 104448
        cudaFuncSetAttribute(attn_tc, cudaFuncAttributeMaxDynamicSharedMemorySize, (int)smem);
        dim3 grid(T_ / 128, H_, B_);
        attn_tc<<<grid, 256, smem>>>(y);
    }

    // 4) output projection: [4096,2048] x [2048,2048]^T -> out fp32
    {
        dim3 grid(C_ / 128, (B_ * T_) / 128);
        gemm_f16<<<grid, 128, gemm_smem>>>(y, wp, out, B_ * T_, C_, C_);
    }
}

// round 14
// speedup vs baseline: 2.1216x; 1.0179x over previous
#include <cuda_runtime.h>
#include <cuda_fp16.h>
#include <math.h>
#include <float.h>
#include <stdint.h>

#define B_ 2
#define T_ 2048
#define C_ 2048
#define H_ 16
#define D_ 128
#define F_ (3*C_)

// ---------------- scratch ----------------
__device__ float  g_qkv[(size_t)B_ * T_ * F_];      // raw fp32 GEMM output
__device__ __half g_q[(size_t)B_ * H_ * T_ * D_];   // fp16 (scaled by gain/sqrtD*log2e)
__device__ __half g_k[(size_t)B_ * H_ * T_ * D_];
__device__ __half g_v[(size_t)B_ * H_ * T_ * D_];
__device__ __half g_y[(size_t)B_ * T_ * C_];
__device__ __half g_xh[(size_t)B_ * T_ * C_];       // fp16 x
__device__ __half g_wq[(size_t)F_ * C_];            // fp16 Wqkv
__device__ __half g_wp[(size_t)C_ * C_];            // fp16 Wproj

// ---------------- helpers ----------------
#define MMA_F16(c, a, b)                                                      \
  asm volatile(                                                               \
      "mma.sync.aligned.m16n8k16.row.col.f32.f16.f16.f32 "                    \
      "{%0,%1,%2,%3}, {%4,%5,%6,%7}, {%8,%9}, {%0,%1,%2,%3};"                 \
      : "+f"((c)[0]), "+f"((c)[1]), "+f"((c)[2]), "+f"((c)[3])                \
      : "r"((a)[0]), "r"((a)[1]), "r"((a)[2]), "r"((a)[3]),                   \
        "r"((b)[0]), "r"((b)[1]))

#define LDSM_X4(r, addr)                                                      \
  asm volatile("ldmatrix.sync.aligned.m8n8.x4.shared.b16 {%0,%1,%2,%3}, [%4];"\
      : "=r"((r)[0]), "=r"((r)[1]), "=r"((r)[2]), "=r"((r)[3])                \
      : "r"(addr))

#define LDSM_X4_T(r, addr)                                                    \
  asm volatile("ldmatrix.sync.aligned.m8n8.x4.trans.shared.b16 {%0,%1,%2,%3}, [%4];"\
      : "=r"((r)[0]), "=r"((r)[1]), "=r"((r)[2]), "=r"((r)[3])                \
      : "r"(addr))

__device__ __forceinline__ uint32_t smem_u32(const void* p) {
    return (uint32_t)__cvta_generic_to_shared(p);
}
__device__ __forceinline__ void cp16(void* sdst, const void* gsrc) {
    uint32_t s = smem_u32(sdst);
    asm volatile("cp.async.cg.shared.global [%0], [%1], 16;" :: "r"(s), "l"(gsrc));
}
#define CP_COMMIT() asm volatile("cp.async.commit_group;" ::)
#define CP_WAIT1()  asm volatile("cp.async.wait_group 1;" ::)
#define CP_WAIT0()  asm volatile("cp.async.wait_group 0;" ::)

__device__ __forceinline__ uint32_t packh2(float x, float y) {
    __half2 h = __floats2half2_rn(x, y);
    return *(uint32_t*)&h;
}
__device__ __forceinline__ float exp2x(float x) {
    float y; asm("ex2.approx.ftz.f32 %0, %1;" : "=f"(y) : "f"(x)); return y;
}

// ---------------- fp32 -> fp16 convert (8 elems/thread) ----------------
__global__ __launch_bounds__(256) void cvt_f16_kernel(const float4* __restrict__ src,
                                                      uint4* __restrict__ dst, int n8)
{
    int i = blockIdx.x * blockDim.x + threadIdx.x;
    if (i < n8) {
        float4 a = src[2 * i];
        float4 b = src[2 * i + 1];
        __half2 h0 = __floats2half2_rn(a.x, a.y);
        __half2 h1 = __floats2half2_rn(a.z, a.w);
        __half2 h2 = __floats2half2_rn(b.x, b.y);
        __half2 h3 = __floats2half2_rn(b.z, b.w);
        uint4 o = {*(uint32_t*)&h0, *(uint32_t*)&h1, *(uint32_t*)&h2, *(uint32_t*)&h3};
        dst[i] = o;
    }
}

// ---------------- fp16 GEMM (unchanged) --------------------------------------
#define HSTR 72
#define HS_SZ (128 * HSTR)

__global__ __launch_bounds__(128, 2) void gemm_f16(const __half* __restrict__ A,
                                                   const __half* __restrict__ Bm,
                                                   float* __restrict__ Cm,
                                                   int M, int N, int K)
{
    extern __shared__ __half hsm[];
    __half* As = hsm;
    __half* Bs = hsm + 2 * HS_SZ;

    const int tid  = threadIdx.x;
    const int warp = tid >> 5;
    const int lane = tid & 31;
    const int g    = lane >> 2;
    const int tg   = lane & 3;
    const int lm8  = lane & 7;
    const int lq   = lane >> 3;
    const int wm   = (warp >> 1) * 64;
    const int wn   = (warp & 1) * 64;
    const int m0   = blockIdx.y * 128;
    const int n0   = blockIdx.x * 128;

    const uint32_t sbA = smem_u32(As);
    const uint32_t sbB = smem_u32(Bs);
    const uint32_t aBase = sbA + (uint32_t)((wm + lm8 + ((lq & 1) << 3)) * HSTR) * 2
                               + ((uint32_t)(lq >> 1) << 4);
    const uint32_t bBase = sbB + (uint32_t)((wn + lm8 + ((lq >> 1) << 3)) * HSTR) * 2
                               + ((uint32_t)(lq & 1) << 4);
    const uint32_t stageBytes = HS_SZ * 2;

    float acc[4][8][4];
#pragma unroll
    for (int mi = 0; mi < 4; mi++)
#pragma unroll
        for (int ni = 0; ni < 8; ni++)
#pragma unroll
            for (int c = 0; c < 4; c++) acc[mi][ni][c] = 0.f;

    uint32_t af[2][4][4], bq[2][4][4];

    auto load_stage = [&](int s, int k0) {
#pragma unroll
        for (int t = 0; t < 8; t++) {
            int cid = tid + t * 128;
            int row = cid >> 3;
            int ch8 = (cid & 7) * 8;
            cp16(&As[(size_t)s * HS_SZ + row * HSTR + ch8],
                 A + (size_t)(m0 + row) * K + k0 + ch8);
            cp16(&Bs[(size_t)s * HS_SZ + row * HSTR + ch8],
                 Bm + (size_t)(n0 + row) * K + k0 + ch8);
        }
    };

#define LD_FRAG(buf, sOff, ks)                                                  \
    do {                                                                        \
        _Pragma("unroll")                                                       \
        for (int mi = 0; mi < 4; mi++)                                          \
            LDSM_X4(af[buf][mi], aBase + (sOff) + (uint32_t)(mi * 16 * HSTR * 2) + (ks) * 32); \
        _Pragma("unroll")                                                       \
        for (int p = 0; p < 4; p++)                                             \
            LDSM_X4(bq[buf][p], bBase + (sOff) + (uint32_t)(p * 16 * HSTR * 2) + (ks) * 32);   \
    } while (0)

#define DO_MMA(buf)                                                             \
    do {                                                                        \
        _Pragma("unroll")                                                       \
        for (int mi = 0; mi < 4; mi++)                                          \
            _Pragma("unroll")                                                   \
            for (int p = 0; p < 4; p++) {                                       \
                MMA_F16(acc[mi][2 * p],     af[buf][mi], bq[buf][p]);           \
                MMA_F16(acc[mi][2 * p + 1], af[buf][mi], bq[buf][p] + 2);       \
            }                                                                   \
    } while (0)

    load_stage(0, 0);  CP_COMMIT();
    load_stage(1, 64); CP_COMMIT();
    CP_WAIT1();
    __syncthreads();

    const int nK = K / 64;
    int cur = 0;
    LD_FRAG(0, 0u, 0);

    for (int kt = 0; kt < nK; kt++) {
        const uint32_t sOff = (uint32_t)cur * stageBytes;
#pragma unroll
        for (int ks = 0; ks < 4; ks++) {
            const int cb = ks & 1;
            if (ks < 3) {
                if (cb) LD_FRAG(0, sOff, ks + 1);
                else    LD_FRAG(1, sOff, ks + 1);
            }
            if (cb) DO_MMA(1); else DO_MMA(0);
        }
        __syncthreads();
        if (kt + 2 < nK) load_stage(cur, (kt + 2) * 64);
        CP_COMMIT();
        CP_WAIT1();
        __syncthreads();
        cur ^= 1;
        if (kt + 1 < nK)
            LD_FRAG(0, (uint32_t)cur * stageBytes, 0);
    }

#pragma unroll
    for (int mi = 0; mi < 4; mi++) {
#pragma unroll
        for (int ni = 0; ni < 8; ni++) {
            const int r = m0 + wm + mi * 16 + g;
            const int c = n0 + wn + ni * 8 + 2 * tg;
            float2 v0 = {acc[mi][ni][0], acc[mi][ni][1]};
            float2 v1 = {acc[mi][ni][2], acc[mi][ni][3]};
            *(float2*)&Cm[(size_t)r * N + c]       = v0;
            *(float2*)&Cm[(size_t)(r + 8) * N + c] = v1;
        }
    }
#undef LD_FRAG
#undef DO_MMA
}

// ---------------- RoPE + split + gain-fold (emits fp16, q scaled by log2e) ---
__global__ __launch_bounds__(256) void rope_kernel(const float* __restrict__ gain,
                                                   const float* __restrict__ cosb,
                                                   const float* __restrict__ sinb)
{
    int idx = blockIdx.x * blockDim.x + threadIdx.x;
    int d = idx & 63;
    int h = (idx >> 6) & 15;
    int t = (idx >> 10) & 2047;
    int b = idx >> 21;

    size_t base = ((size_t)(b * T_ + t)) * F_ + h * D_;
    float c = cosb[t * 64 + d];
    float s = sinb[t * 64 + d];

    float q1 = g_qkv[base + d],            q2 = g_qkv[base + d + 64];
    float k1 = g_qkv[base + C_ + d],       k2 = g_qkv[base + C_ + d + 64];
    float v1 = g_qkv[base + 2 * C_ + d],   v2 = g_qkv[base + 2 * C_ + d + 64];

    // fold softmax scale AND log2(e) into q (softmax done in exp2 domain)
    float gn = gain[h] * rsqrtf((float)D_) * 1.4426950408889634f;
    size_t ob = ((size_t)((b * H_ + h) * T_ + t)) * D_;

    g_q[ob + d]      = __float2half_rn((q1 * c - q2 * s) * gn);
    g_q[ob + d + 64] = __float2half_rn((q2 * c + q1 * s) * gn);
    g_k[ob + d]      = __float2half_rn(k1 * c - k2 * s);
    g_k[ob + d + 64] = __float2half_rn(k2 * c + k1 * s);
    g_v[ob + d]      = __float2half_rn(v1);
    g_v[ob + d + 64] = __float2half_rn(v2);
}

// ---------------- fp16 flash attention: 64x64 tiles, 128 thr, 2 CTAs/SM ------
#define QH 136    // halves per row (272B stride, conflict-free)

__global__ __launch_bounds__(128, 2) void attn_tc(__half* __restrict__ Y)
{
    extern __shared__ __half ham[];
    __half* sQ = ham;                        // [64][QH]
    __half* sK = ham + 64 * QH;              // [64][QH]
    __half* sV = ham + 128 * QH;             // [64][QH]

    const int tid  = threadIdx.x;
    const int warp = tid >> 5;               // 0..3
    const int lane = tid & 31;
    const int g    = lane >> 2;
    const int tg   = lane & 3;
    const int lm8  = lane & 7;
    const int lq   = lane >> 3;
    // LPT: heaviest q-blocks first
    const int qb = (T_ / 64 - 1) - blockIdx.x;
    const int h  = blockIdx.y;
    const int b  = blockIdx.z;
    const int q0 = qb * 64;
    const size_t bh = ((size_t)(b * H_ + h)) * T_ * D_;

    const uint32_t qAddr = smem_u32(sQ)
        + (uint32_t)((16 * warp + lm8 + ((lq & 1) << 3)) * QH) * 2
        + ((uint32_t)(lq >> 1) << 4);
    const uint32_t kAddr = smem_u32(sK)
        + (uint32_t)((lm8 + ((lq >> 1) << 3)) * QH) * 2
        + ((uint32_t)(lq & 1) << 4);
    const uint32_t vAddr = smem_u32(sV)
        + (uint32_t)((lm8 + ((lq & 1) << 3)) * QH) * 2
        + ((uint32_t)(lq >> 1) << 4);

    // loaders: 64 rows x 16 16B-chunks = 1024 -> 8/thread
    auto load_k = [&](int k0) {
#pragma unroll
        for (int i = 0; i < 8; i++) {
            int e = tid + i * 128;
            int row = e >> 4;
            int col = (e & 15) * 8;
            cp16(&sK[row * QH + col], g_k + bh + (size_t)(k0 + row) * D_ + col);
        }
    };
    auto load_v = [&](int k0) {
#pragma unroll
        for (int i = 0; i < 8; i++) {
            int e = tid + i * 128;
            int row = e >> 4;
            int col = (e & 15) * 8;
            cp16(&sV[row * QH + col], g_v + bh + (size_t)(k0 + row) * D_ + col);
        }
    };

    // prologue: K_0 in flight; Q tile via plain stores
    load_k(0); CP_COMMIT();
    for (int i = 0; i < 8; i++) {
        int e = tid + i * 128;
        int row = e >> 4;
        int col = (e & 15) * 8;
        *(uint4*)&sQ[row * QH + col] = *(const uint4*)(g_q + bh + (size_t)(q0 + row) * D_ + col);
    }
    __syncthreads();

    // hoist Q fragments (loop-invariant)
    uint32_t qf[8][4];
#pragma unroll
    for (int ks = 0; ks < 8; ks++)
        LDSM_X4(qf[ks], qAddr + ks * 32);

    float yacc[16][4];
#pragma unroll
    for (int nt = 0; nt < 16; nt++)
#pragma unroll
        for (int c = 0; c < 4; c++) yacc[nt][c] = 0.f;
    float m0 = -1e30f, m1 = -1e30f, l0 = 0.f, l1 = 0.f;

    for (int kt = 0; kt <= qb; kt++) {
        const int k0 = kt * 64;

        CP_WAIT0();
        __syncthreads();                 // K_kt visible; prior PV done

        load_v(k0); CP_COMMIT();         // V_kt overlaps S + softmax

        // S = Q K^T  (64 keys -> 4 n16 groups)
        float sacc[8][4];
#pragma unroll
        for (int nt = 0; nt < 8; nt++)
#pragma unroll
            for (int c = 0; c < 4; c++) sacc[nt][c] = 0.f;

#pragma unroll
        for (int ks = 0; ks < 8; ks++) {
#pragma unroll
            for (int p = 0; p < 4; p++) {
                uint32_t bqv[4];
                LDSM_X4(bqv, kAddr + (uint32_t)(p * 16 * QH * 2) + ks * 32);
                MMA_F16(sacc[2 * p],     qf[ks], bqv);
                MMA_F16(sacc[2 * p + 1], qf[ks], bqv + 2);
            }
        }

        // causal mask on diagonal tile
        if (kt == qb) {
            const int r0g = q0 + 16 * warp + g;
            const int r1g = r0g + 8;
#pragma unroll
            for (int nt = 0; nt < 8; nt++) {
                int c0 = k0 + nt * 8 + 2 * tg;
                if (c0     > r0g) sacc[nt][0] = -1e30f;
                if (c0 + 1 > r0g) sacc[nt][1] = -1e30f;
                if (c0     > r1g) sacc[nt][2] = -1e30f;
                if (c0 + 1 > r1g) sacc[nt][3] = -1e30f;
            }
        }

        // online softmax in exp2 domain
        float mx0 = -1e30f, mx1 = -1e30f;
#pragma unroll
        for (int nt = 0; nt < 8; nt++) {
            mx0 = fmaxf(mx0, fmaxf(sacc[nt][0], sacc[nt][1]));
            mx1 = fmaxf(mx1, fmaxf(sacc[nt][2], sacc[nt][3]));
        }
        mx0 = fmaxf(mx0, __shfl_xor_sync(0xffffffffu, mx0, 1));
        mx0 = fmaxf(mx0, __shfl_xor_sync(0xffffffffu, mx0, 2));
        mx1 = fmaxf(mx1, __shfl_xor_sync(0xffffffffu, mx1, 1));
        mx1 = fmaxf(mx1, __shfl_xor_sync(0xffffffffu, mx1, 2));

        float nm0 = fmaxf(m0, mx0), nm1 = fmaxf(m1, mx1);
        float cf0 = exp2x(m0 - nm0), cf1 = exp2x(m1 - nm1);
        m0 = nm0; m1 = nm1;

        float rs0 = 0.f, rs1 = 0.f;
#pragma unroll
        for (int nt = 0; nt < 8; nt++) {
            sacc[nt][0] = exp2x(sacc[nt][0] - nm0);
            sacc[nt][1] = exp2x(sacc[nt][1] - nm0);
            sacc[nt][2] = exp2x(sacc[nt][2] - nm1);
            sacc[nt][3] = exp2x(sacc[nt][3] - nm1);
            rs0 += sacc[nt][0] + sacc[nt][1];
            rs1 += sacc[nt][2] + sacc[nt][3];
        }
        rs0 += __shfl_xor_sync(0xffffffffu, rs0, 1);
        rs0 += __shfl_xor_sync(0xffffffffu, rs0, 2);
        rs1 += __shfl_xor_sync(0xffffffffu, rs1, 1);
        rs1 += __shfl_xor_sync(0xffffffffu, rs1, 2);
        l0 = l0 * cf0 + rs0;
        l1 = l1 * cf1 + rs1;

#pragma unroll
        for (int nt = 0; nt < 16; nt++) {
            yacc[nt][0] *= cf0; yacc[nt][1] *= cf0;
            yacc[nt][2] *= cf1; yacc[nt][3] *= cf1;
        }

        // P fragments: register repack (4 k16 steps over 64 keys)
        uint32_t pf[4][4];
#pragma unroll
        for (int ks = 0; ks < 4; ks++) {
            pf[ks][0] = packh2(sacc[2 * ks][0],     sacc[2 * ks][1]);
            pf[ks][1] = packh2(sacc[2 * ks][2],     sacc[2 * ks][3]);
            pf[ks][2] = packh2(sacc[2 * ks + 1][0], sacc[2 * ks + 1][1]);
            pf[ks][3] = packh2(sacc[2 * ks + 1][2], sacc[2 * ks + 1][3]);
        }

        CP_WAIT0();
        __syncthreads();                 // V_kt visible; all warps done with K

        if (kt < qb) { load_k(k0 + 64); CP_COMMIT(); }   // K_{kt+1} overlaps PV

        // yacc += P V  (V^T via ldmatrix.trans; keys=64 -> 4 k16 steps)
#pragma unroll
        for (int ks = 0; ks < 4; ks++) {
#pragma unroll
            for (int p = 0; p < 8; p++) {
                uint32_t bqv[4];
                LDSM_X4_T(bqv, vAddr + (uint32_t)(ks * 16 * QH * 2) + p * 32);
                MMA_F16(yacc[2 * p],     pf[ks], bqv);
                MMA_F16(yacc[2 * p + 1], pf[ks], bqv + 2);
            }
        }
    }

    // epilogue: fp16 y
    const float inv0 = 1.f / l0;
    const float inv1 = 1.f / l1;
    const int r0g = q0 + 16 * warp + g;
    const int r1g = r0g + 8;
#pragma unroll
    for (int nt = 0; nt < 16; nt++) {
        int col = h * D_ + nt * 8 + 2 * tg;
        *(__half2*)&Y[(size_t)(b * T_ + r0g) * C_ + col] =
            __floats2half2_rn(yacc[nt][0] * inv0, yacc[nt][1] * inv0);
        *(__half2*)&Y[(size_t)(b * T_ + r1g) * C_ + col] =
            __floats2half2_rn(yacc[nt][2] * inv1, yacc[nt][3] * inv1);
    }
}

// ---------------- launch ----------------
extern "C" void kernel_launch(void* const* d_in, const int* in_sizes, int n_in,
                              void* d_out, int out_size)
{
    const float* x     = (const float*)d_in[0];
    const float* Wqkv  = (const float*)d_in[1];
    const float* Wproj = (const float*)d_in[2];
    const float* gain  = (const float*)d_in[3];
    const float* cosb  = (const float*)d_in[4];
    const float* sinb  = (const float*)d_in[5];
    float* out = (float*)d_out;

    float* qkv;
    __half *y, *xh, *wq, *wp;
    cudaGetSymbolAddress((void**)&qkv, g_qkv);
    cudaGetSymbolAddress((void**)&y,   g_y);
    cudaGetSymbolAddress((void**)&xh,  g_xh);
    cudaGetSymbolAddress((void**)&wq,  g_wq);
    cudaGetSymbolAddress((void**)&wp,  g_wp);

    const size_t gemm_smem = (size_t)4 * HS_SZ * sizeof(__half);   // 73728
    cudaFuncSetAttribute(gemm_f16, cudaFuncAttributeMaxDynamicSharedMemorySize, (int)gemm_smem);

    // 0) convert inputs to fp16
    {
        int n8x = (B_ * T_ * C_) / 8;
        cvt_f16_kernel<<<(n8x + 255) / 256, 256>>>((const float4*)x, (uint4*)xh, n8x);
        int n8q = (F_ * C_) / 8;
        cvt_f16_kernel<<<(n8q + 255) / 256, 256>>>((const float4*)Wqkv, (uint4*)wq, n8q);
        int n8p = (C_ * C_) / 8;
        cvt_f16_kernel<<<(n8p + 255) / 256, 256>>>((const float4*)Wproj, (uint4*)wp, n8p);
    }

    // 1) QKV GEMM
    {
        dim3 grid(F_ / 128, (B_ * T_) / 128);
        gemm_f16<<<grid, 128, gemm_smem>>>(xh, wq, qkv, B_ * T_, F_, C_);
    }

    // 2) RoPE + split + gain (emits fp16, q pre-scaled for exp2 softmax)
    {
        int total = B_ * T_ * H_ * 64;
        rope_kernel<<<total / 256, 256>>>(gain, cosb, sinb);
    }

    // 3) attention: 64x64 tiles, 128 threads, 2 CTAs/SM
    {
        size_t smem = (size_t)3 * 64 * QH * sizeof(__half);   // 52224
        cudaFuncSetAttribute(attn_tc, cudaFuncAttributeMaxDynamicSharedMemorySize, (int)smem);
        dim3 grid(T_ / 64, H_, B_);
        attn_tc<<<grid, 128, smem>>>(y);
    }

    // 4) output projection
    {
        dim3 grid(C_ / 128, (B_ * T_) / 128);
        gemm_f16<<<grid, 128, gemm_smem>>>(y, wp, out, B_ * T_, C_, C_);
    }
}